// round 12
// baseline (speedup 1.0000x reference)
#include <cuda_runtime.h>
#include <cstdint>

#define NN 2048
#define IN_DIM 1024
#define MLPW 16
#define HIDD 256
#define L2DIM 64
#define NCLS 4
#define YSPL 4
#define HSPL 4

// ---------------- scratch (device globals; no allocation) ----------------
__device__ float g_A[(size_t)NN * NN];          // A = adj*mask + I (tf32-rounded)
__device__ float g_Xt[(size_t)NN * IN_DIM];     // tf32-rounded x [2048][1024]
__device__ float g_W12t[(size_t)L2DIM * IN_DIM];// tf32 (Wg1@Wl2)^T [64][1024]
__device__ float g_Yp[YSPL][(size_t)L2DIM * NN];// x@W12 split-K partials (fp32, ^T)
__device__ float g_Yt[(size_t)L2DIM * NN];      // tf32 (dc ⊙ x@W12)^T [64][2048]
__device__ float g_Hp[HSPL][(size_t)NN * L2DIM];// A@Y split-K partials (fp32)
__device__ float g_HW[(size_t)NN * NCLS];       // dc-scaled hid@Wg2
__device__ float g_rowsum[NN];
__device__ float g_colsum[NN];

__device__ __forceinline__ float rsqrt_pos(float v) {
    return v > 0.f ? rsqrtf(v) : 0.f;
}
__device__ __forceinline__ uint32_t f2tf32(float f) {
    uint32_t u;
    asm("cvt.rna.tf32.f32 %0, %1;" : "=r"(u) : "f"(f));
    return u;
}

// ---------------- f32x2 packed helpers -------------------------------------
__device__ __forceinline__ unsigned long long pk2(float x, float y) {
    unsigned long long r;
    asm("mov.b64 %0, {%1, %2};" : "=l"(r) : "f"(x), "f"(y));
    return r;
}
__device__ __forceinline__ float2 upk2(unsigned long long v) {
    float2 r;
    asm("mov.b64 {%0, %1}, %2;" : "=f"(r.x), "=f"(r.y) : "l"(v));
    return r;
}
__device__ __forceinline__ unsigned long long fma2p(unsigned long long a,
                                                   unsigned long long b,
                                                   unsigned long long c) {
    unsigned long long r;
    asm("fma.rn.f32x2 %0, %1, %2, %3;" : "=l"(r) : "l"(a), "l"(b), "l"(c));
    return r;
}
__device__ __forceinline__ unsigned long long relu2p(unsigned long long v) {
    uint32_t lo = (uint32_t)v, hi = (uint32_t)(v >> 32);
    lo &= ~(uint32_t)((int32_t)lo >> 31);
    hi &= ~(uint32_t)((int32_t)hi >> 31);
    return (unsigned long long)lo | ((unsigned long long)hi << 32);
}

// ---------------- async copy / ldmatrix helpers ----------------------------
__device__ __forceinline__ void cp_async16(uint32_t smem, const void* gptr) {
    asm volatile("cp.async.cg.shared.global [%0], [%1], 16;\n" ::"r"(smem), "l"(gptr));
}
__device__ __forceinline__ void cp_commit() {
    asm volatile("cp.async.commit_group;\n");
}
template <int N>
__device__ __forceinline__ void cp_wait() {
    asm volatile("cp.async.wait_group %0;\n" ::"n"(N));
}
__device__ __forceinline__ void ldsm4(uint32_t* r, uint32_t addr) {
    asm volatile("ldmatrix.sync.aligned.m8n8.x4.shared.b16 {%0,%1,%2,%3}, [%4];"
                 : "=r"(r[0]), "=r"(r[1]), "=r"(r[2]), "=r"(r[3]) : "r"(addr));
}
__device__ __forceinline__ void mma_tf32(float* c,
                                         const uint32_t* a,
                                         uint32_t b0, uint32_t b1) {
    asm volatile(
        "mma.sync.aligned.m16n8k8.row.col.f32.tf32.tf32.f32 "
        "{%0,%1,%2,%3}, {%4,%5,%6,%7}, {%8,%9}, {%0,%1,%2,%3};"
        : "+f"(c[0]), "+f"(c[1]), "+f"(c[2]), "+f"(c[3])
        : "r"(a[0]), "r"(a[1]), "r"(a[2]), "r"(a[3]), "r"(b0), "r"(b1));
}

// ---------------- kernel 1: edge MLP (f32x2) + round x + W12t --------------
// blocks 0..2047: one A-row each, packed column pairs; zero colsum[i]
// blocks 2048..2559: tf32-round x
// blocks 2560..2687: W12t[c][r] = tf32(sum_k Wg1[r][k]*Wl2[k][c]), 8 rows/blk
__global__ __launch_bounds__(256) void edge_kernel(
    const float* __restrict__ adj, const float* __restrict__ xdeg,
    const float* __restrict__ ydeg, const float* __restrict__ Wm1,
    const float* __restrict__ bm1, const float* __restrict__ Wm2,
    const float* __restrict__ bm2, const float* __restrict__ x,
    const float* __restrict__ Wg1, const float* __restrict__ Wl2) {
    int b = blockIdx.x;
    int tid = threadIdx.x;
    if (b < NN) {
        __shared__ unsigned long long sW1p[48], sb1p[16], sdwp[16];
        __shared__ float sb2s[2];
        if (tid < 48) { float w = Wm1[tid]; sW1p[tid] = pk2(w, w); }
        if (tid < 16) { float w = bm1[tid]; sb1p[tid] = pk2(w, w); }
        if (tid < 16) {
            float dw = Wm2[2 * tid + 1] - Wm2[2 * tid];
            sdwp[tid] = pk2(dw, dw);
        }
        if (tid < 2) sb2s[tid] = bm2[tid];
        int i = b;
        if (tid == 0) g_colsum[i] = 0.f;   // colsum_kernel runs strictly after
        __syncthreads();

        const float2* arow2 = reinterpret_cast<const float2*>(adj  + (size_t)i * NN);
        const float2* xrow2 = reinterpret_cast<const float2*>(xdeg + (size_t)i * NN);
        const float2* yrow2 = reinterpret_cast<const float2*>(ydeg + (size_t)i * NN);
        float2* Arow2 = reinterpret_cast<float2*>(g_A + (size_t)i * NN);
        const float db = sb2s[1] - sb2s[0];
        const unsigned long long dbp = pk2(db, db);

        float rsum = 0.f;
#pragma unroll
        for (int t = 0; t < 4; t++) {
            int p = tid + t * 256;         // pair index (cols 2p, 2p+1)
            float2 av = arow2[p], xv = xrow2[p], yv = yrow2[p];
            unsigned long long a2 = pk2(av.x, av.y);
            unsigned long long x2 = pk2(xv.x, xv.y);
            unsigned long long y2 = pk2(yv.x, yv.y);
            unsigned long long dl2 = dbp;
#pragma unroll
            for (int k = 0; k < MLPW; k++) {
                unsigned long long h = fma2p(y2, sW1p[32 + k], sb1p[k]);
                h = fma2p(x2, sW1p[16 + k], h);
                h = fma2p(a2, sW1p[k], h);
                h = relu2p(h);
                dl2 = fma2p(h, sdwp[k], dl2);
            }
            float2 dl = upk2(dl2);
            float th0, th1;
            float d0 = 0.5f * dl.x, d1 = 0.5f * dl.y;
            asm("tanh.approx.f32 %0, %1;" : "=f"(th0) : "f"(d0));
            asm("tanh.approx.f32 %0, %1;" : "=f"(th1) : "f"(d1));
            float m0 = fmaf(0.5f, th0, 0.5f);
            float m1 = fmaf(0.5f, th1, 0.5f);
            float A0 = av.x * m0 + (2 * p == i ? 1.f : 0.f);
            float A1 = av.y * m1 + (2 * p + 1 == i ? 1.f : 0.f);
            A0 = __uint_as_float(f2tf32(A0));
            A1 = __uint_as_float(f2tf32(A1));
            Arow2[p] = make_float2(A0, A1);
            rsum += A0 + A1;
        }
        for (int off = 16; off; off >>= 1) rsum += __shfl_down_sync(0xffffffffu, rsum, off);
        __shared__ float red[8];
        if ((tid & 31) == 0) red[tid >> 5] = rsum;
        __syncthreads();
        if (tid == 0) {
            float s = 0.f;
#pragma unroll
            for (int w = 0; w < 8; w++) s += red[w];
            g_rowsum[i] = s;
        }
    } else if (b < NN + 512) {
        size_t idx4 = (size_t)(b - NN) * 1024 + tid;
        const float4* src = reinterpret_cast<const float4*>(x);
        float4* dst = reinterpret_cast<float4*>(g_Xt);
#pragma unroll
        for (int t = 0; t < 4; t++) {
            float4 v = src[idx4 + t * 256];
            uint4 u;
            u.x = f2tf32(v.x); u.y = f2tf32(v.y); u.z = f2tf32(v.z); u.w = f2tf32(v.w);
            dst[idx4 + t * 256] = *reinterpret_cast<float4*>(&u);
        }
    } else {
        // W12t: 128 blocks, each computes rows [rbase, rbase+8) of W12 for all 64 cols
        __shared__ float sW[8][256];
        int rbase = (b - NN - 512) * 8;
#pragma unroll
        for (int t = 0; t < 8; t++) {
            int idx = t * 256 + tid;
            sW[idx >> 8][idx & 255] = Wg1[(size_t)(rbase + (idx >> 8)) * HIDD + (idx & 255)];
        }
        __syncthreads();
        int c = tid & 63, rr = tid >> 6;   // rr 0..3
#pragma unroll
        for (int half = 0; half < 2; half++) {
            int rl = rr + half * 4;
            float acc = 0.f;
#pragma unroll 4
            for (int k = 0; k < HIDD; k++)
                acc = fmaf(sW[rl][k], __ldg(&Wl2[k * L2DIM + c]), acc);
            g_W12t[(size_t)c * IN_DIM + rbase + rl] = __uint_as_float(f2tf32(acc));
        }
    }
}

// ---------------- colsum: 512 CTAs, 8 rows each ----------------------------
__global__ __launch_bounds__(256) void colsum_kernel() {
    int j4 = blockIdx.x * 256 + threadIdx.x;     // 0..511 (float4 col)
    int r0 = blockIdx.y * 8;
    const float4* A4 = reinterpret_cast<const float4*>(g_A);
    float sx = 0.f, sy = 0.f, sz = 0.f, sw = 0.f;
#pragma unroll
    for (int i = 0; i < 8; i++) {
        float4 v = A4[(size_t)(r0 + i) * (NN / 4) + j4];
        sx += v.x; sy += v.y; sz += v.z; sw += v.w;
    }
    int j = j4 * 4;
    atomicAdd(&g_colsum[j + 0], sx);
    atomicAdd(&g_colsum[j + 1], sy);
    atomicAdd(&g_colsum[j + 2], sz);
    atomicAdd(&g_colsum[j + 3], sw);
}

// ---------------- tf32 tensor-core GEMM, BK=64, 2-stage, split-K CTAs -----
#define BKK 64
#define HSB 8192      // half-stage bytes per operand (64 rows * 128B)
#define OPB 16384     // per-stage per-operand bytes
#define GEMM_SMEM 65536

template <bool TRANSOUT, int NSPLIT, int CSTRIDE>
__device__ __forceinline__ void gemm_body(const float* __restrict__ A,
                                          const float* __restrict__ Bt,
                                          float* __restrict__ C, int Kd) {
    extern __shared__ __align__(16) uint8_t smem_dyn[];
    const uint32_t sAu = (uint32_t)__cvta_generic_to_shared(smem_dyn);
    const uint32_t sBu = sAu + 2 * OPB;

    const int tid = threadIdx.x;
    const int lane = tid & 31, warp = tid >> 5;
    const int wm = warp & 1, wn = (warp >> 1) & 1, kg = warp >> 2;  // kg 0..1
    const int gid = lane >> 2, tig = lane & 3;
    const int mi = lane >> 3, lr = lane & 7;
    const int bm0 = blockIdx.y * 64, bn0 = blockIdx.x * 64;
    const int kbase = (NSPLIT > 1) ? blockIdx.z * (Kd / NSPLIT) : 0;

    const int ld_row = tid >> 2;           // 0..63
    const int qb = (tid & 3) << 1;         // 0,2,4,6
    const uint32_t off0 = ld_row * 128 + (((qb + 0) ^ (ld_row & 7)) << 4);
    const uint32_t off1 = ld_row * 128 + (((qb + 1) ^ (ld_row & 7)) << 4);
    const float* Ag = A + (size_t)(bm0 + ld_row) * Kd + kbase;
    const float* Bg = Bt + (size_t)(bn0 + ld_row) * Kd + kbase;

    const int arow = wm * 32 + ((mi & 1) << 3) + lr;
    const int brow = wn * 32 + ((mi >> 1) << 3) + lr;
    const uint32_t axr = arow & 7, bxr = brow & 7;
    const uint32_t qselA = mi >> 1, qselB = mi & 1;
    const uint32_t aOff0 = arow * 128, aOff1 = aOff0 + 16 * 128;
    const uint32_t bOff0 = brow * 128, bOff1 = bOff0 + 16 * 128;
    const uint32_t aqj[2] = {(((uint32_t)(kg * 2 + 0) * 2 + qselA) ^ axr) << 4,
                             (((uint32_t)(kg * 2 + 1) * 2 + qselA) ^ axr) << 4};
    const uint32_t bqj[2] = {(((uint32_t)(kg * 2 + 0) * 2 + qselB) ^ bxr) << 4,
                             (((uint32_t)(kg * 2 + 1) * 2 + qselB) ^ bxr) << 4};

    auto issue = [&](int kt, int s) {
#pragma unroll
        for (int h = 0; h < 2; h++) {
            const float* ag = Ag + (size_t)kt * BKK + h * 32;
            const float* bg = Bg + (size_t)kt * BKK + h * 32;
            uint32_t da = sAu + s * OPB + h * HSB;
            uint32_t db = sBu + s * OPB + h * HSB;
            cp_async16(da + off0, ag + qb * 4);
            cp_async16(da + off1, ag + qb * 4 + 4);
            cp_async16(db + off0, bg + qb * 4);
            cp_async16(db + off1, bg + qb * 4 + 4);
        }
    };

    const int niter = (Kd / NSPLIT) / BKK;
    issue(0, 0);
    cp_commit();

    float acc[2][4][4] = {};

    for (int i = 0; i < niter; i++) {
        cp_wait<0>();
        __syncthreads();
        if (i + 1 < niter) { issue(i + 1, (i + 1) & 1); cp_commit(); }
        const int s = i & 1;
#pragma unroll
        for (int h = 0; h < 2; h++) {
            const uint32_t sAs = sAu + s * OPB + h * HSB;
            const uint32_t sBs = sBu + s * OPB + h * HSB;
#pragma unroll
            for (int jj = 0; jj < 2; jj++) {
                uint32_t af0[4], af1[4], bf0[4], bf1[4];
                ldsm4(af0, sAs + aOff0 + aqj[jj]);
                ldsm4(af1, sAs + aOff1 + aqj[jj]);
                ldsm4(bf0, sBs + bOff0 + bqj[jj]);
                ldsm4(bf1, sBs + bOff1 + bqj[jj]);
                mma_tf32(acc[0][0], af0, bf0[0], bf0[1]);
                mma_tf32(acc[0][1], af0, bf0[2], bf0[3]);
                mma_tf32(acc[0][2], af0, bf1[0], bf1[1]);
                mma_tf32(acc[0][3], af0, bf1[2], bf1[3]);
                mma_tf32(acc[1][0], af1, bf0[0], bf0[1]);
                mma_tf32(acc[1][1], af1, bf0[2], bf0[3]);
                mma_tf32(acc[1][2], af1, bf1[0], bf1[1]);
                mma_tf32(acc[1][3], af1, bf1[2], bf1[3]);
            }
        }
    }

    // ---- 2-way K-split reduction through smem -----------------------------
    __syncthreads();
    float* sred = reinterpret_cast<float*>(smem_dyn);
    const int pi = wm * 2 + wn;
    if (kg == 1) {
#pragma unroll
        for (int mt = 0; mt < 2; mt++)
#pragma unroll
            for (int nt = 0; nt < 4; nt++) {
                int r = mt * 16 + gid, c = nt * 8 + 2 * tig;
                float* base = sred + pi * 1056;
                base[r * 33 + c] = acc[mt][nt][0];
                base[r * 33 + c + 1] = acc[mt][nt][1];
                base[(r + 8) * 33 + c] = acc[mt][nt][2];
                base[(r + 8) * 33 + c + 1] = acc[mt][nt][3];
            }
    }
    __syncthreads();
    if (kg == 0) {
#pragma unroll
        for (int mt = 0; mt < 2; mt++) {
            int r = mt * 16 + gid;
            const float* base = sred + pi * 1056;
            int gr0 = bm0 + wm * 32 + r;
            int gr1 = gr0 + 8;
#pragma unroll
            for (int nt = 0; nt < 4; nt++) {
                int c = nt * 8 + 2 * tig;
                float v00 = acc[mt][nt][0] + base[r * 33 + c];
                float v01 = acc[mt][nt][1] + base[r * 33 + c + 1];
                float v10 = acc[mt][nt][2] + base[(r + 8) * 33 + c];
                float v11 = acc[mt][nt][3] + base[(r + 8) * 33 + c + 1];
                if (TRANSOUT) {
                    int n0 = bn0 + wn * 32 + c;
                    C[(size_t)n0 * NN + gr0] = v00;
                    C[(size_t)(n0 + 1) * NN + gr0] = v01;
                    C[(size_t)n0 * NN + gr1] = v10;
                    C[(size_t)(n0 + 1) * NN + gr1] = v11;
                } else {
                    int col = bn0 + wn * 32 + c;
                    *reinterpret_cast<float2*>(&C[(size_t)gr0 * CSTRIDE + col]) =
                        make_float2(v00, v01);
                    *reinterpret_cast<float2*>(&C[(size_t)gr1 * CSTRIDE + col]) =
                        make_float2(v10, v11);
                }
            }
        }
    }
}

// Y: g_Yp[z] = (x @ W12)^T partial over K-quarter z; M=2048 N=64 K=1024
__global__ __launch_bounds__(256) void y_kernel() {
    gemm_body<true, YSPL, 0>(g_Xt, g_W12t, g_Yp[blockIdx.z], IN_DIM);
}
// HID-GEMM: g_Hp[z] = (g_A @ Y) partial over K-quarter z; M=2048 N=64 K=2048
__global__ __launch_bounds__(256) void hidg_kernel() {
    gemm_body<false, HSPL, L2DIM>(g_A, g_Yt, g_Hp[blockIdx.z], NN);
}

// ---------------- ycomb: Yt = tf32(dc ⊙ sum_z Yp) --------------------------
__global__ __launch_bounds__(256) void ycomb_kernel() {
    int idx = blockIdx.x * 256 + threadIdx.x;   // 32768 float4s
    int m0 = (idx * 4) & (NN - 1);
    float4 s = reinterpret_cast<const float4*>(g_Yp[0])[idx];
#pragma unroll
    for (int z = 1; z < YSPL; z++) {
        float4 v = reinterpret_cast<const float4*>(g_Yp[z])[idx];
        s.x += v.x; s.y += v.y; s.z += v.z; s.w += v.w;
    }
    uint4 u;
    u.x = f2tf32(s.x * rsqrt_pos(g_colsum[m0 + 0]));
    u.y = f2tf32(s.y * rsqrt_pos(g_colsum[m0 + 1]));
    u.z = f2tf32(s.z * rsqrt_pos(g_colsum[m0 + 2]));
    u.w = f2tf32(s.w * rsqrt_pos(g_colsum[m0 + 3]));
    reinterpret_cast<float4*>(g_Yt)[idx] = *reinterpret_cast<float4*>(&u);
}

// ---------------- finish: hid = dr*sum_z Hp + bl2;  HW = dc*(hid@Wg2) ------
__global__ __launch_bounds__(256) void hid_finish_kernel(const float* __restrict__ bl2,
                                                         const float* __restrict__ Wg2,
                                                         float* __restrict__ hid_out) {
    __shared__ float sHid[16][L2DIM + 1];
    int tid = threadIdx.x;
    int rowbase = blockIdx.x * 16;

    int c = tid & 63;
    int rq = tid >> 6;   // 0..3
    float b = bl2[c];
#pragma unroll
    for (int it = 0; it < 4; it++) {
        int row = it * 4 + rq;
        size_t idx = (size_t)(rowbase + row) * L2DIM + c;
        float v = 0.f;
#pragma unroll
        for (int z = 0; z < HSPL; z++) v += g_Hp[z][idx];
        v = v * rsqrt_pos(g_rowsum[rowbase + row]) + b;
        hid_out[idx] = v;
        sHid[row][c] = v;
    }
    __syncthreads();
    if (tid < 64) {
        int r = tid >> 2, cls = tid & 3;
        float s = 0.f;
#pragma unroll
        for (int k = 0; k < L2DIM; k++) s = fmaf(sHid[r][k], Wg2[k * NCLS + cls], s);
        g_HW[(size_t)(rowbase + r) * NCLS + cls] = s * rsqrt_pos(g_colsum[rowbase + r]);
    }
}

// ---------------- out[i] = dr[i] * sum_j A[i,j] * HW[j] --------------------
__global__ __launch_bounds__(256) void out_kernel(float* __restrict__ out) {
    int tid = threadIdx.x;
    __shared__ float sHWt[NCLS][NN];
    const float4* hw4 = reinterpret_cast<const float4*>(g_HW);
#pragma unroll
    for (int t = 0; t < NN / 256; t++) {
        int j = tid + t * 256;
        float4 h = hw4[j];            // HW row j: 4 classes
        sHWt[0][j] = h.x; sHWt[1][j] = h.y; sHWt[2][j] = h.z; sHWt[3][j] = h.w;
    }
    __syncthreads();

    const float4* A4 = reinterpret_cast<const float4*>(g_A);
    __shared__ float red[8][4];
    for (int r = 0; r < 8; r++) {
        int i = blockIdx.x * 8 + r;
        float ax = 0.f, ay = 0.f, az = 0.f, aw = 0.f;
#pragma unroll
        for (int t = 0; t < NN / 1024; t++) {
            int j4 = tid + t * 256;
            float4 a = A4[(size_t)i * (NN / 4) + j4];
            const float4 h0 = *reinterpret_cast<const float4*>(&sHWt[0][j4 * 4]);
            const float4 h1 = *reinterpret_cast<const float4*>(&sHWt[1][j4 * 4]);
            const float4 h2 = *reinterpret_cast<const float4*>(&sHWt[2][j4 * 4]);
            const float4 h3 = *reinterpret_cast<const float4*>(&sHWt[3][j4 * 4]);
            ax += a.x * h0.x + a.y * h0.y + a.z * h0.z + a.w * h0.w;
            ay += a.x * h1.x + a.y * h1.y + a.z * h1.z + a.w * h1.w;
            az += a.x * h2.x + a.y * h2.y + a.z * h2.z + a.w * h2.w;
            aw += a.x * h3.x + a.y * h3.y + a.z * h3.z + a.w * h3.w;
        }
        for (int off = 16; off; off >>= 1) {
            ax += __shfl_down_sync(0xffffffffu, ax, off);
            ay += __shfl_down_sync(0xffffffffu, ay, off);
            az += __shfl_down_sync(0xffffffffu, az, off);
            aw += __shfl_down_sync(0xffffffffu, aw, off);
        }
        if ((tid & 31) == 0) {
            int w = tid >> 5;
            red[w][0] = ax; red[w][1] = ay; red[w][2] = az; red[w][3] = aw;
        }
        __syncthreads();
        if (tid < 4) {
            float s = 0.f;
#pragma unroll
            for (int w = 0; w < 8; w++) s += red[w][tid];
            out[i * NCLS + tid] = rsqrt_pos(g_rowsum[i]) * s;
        }
        __syncthreads();
    }
}

// ---------------- launch (single stream, 7 kernels) ------------------------
extern "C" void kernel_launch(void* const* d_in, const int* in_sizes, int n_in,
                              void* d_out, int out_size) {
    const float* x    = (const float*)d_in[0];
    const float* adj  = (const float*)d_in[1];
    const float* xdeg = (const float*)d_in[2];
    const float* ydeg = (const float*)d_in[3];
    const float* Wm1  = (const float*)d_in[4];
    const float* bm1  = (const float*)d_in[5];
    const float* Wm2  = (const float*)d_in[6];
    const float* bm2  = (const float*)d_in[7];
    const float* Wg1  = (const float*)d_in[8];
    const float* Wl2  = (const float*)d_in[9];
    const float* bl2  = (const float*)d_in[10];
    const float* Wg2  = (const float*)d_in[11];

    float* out = (float*)d_out;               // [2048, 4]
    float* hid = out + (size_t)NN * NCLS;     // [2048, 64]

    static bool attr_done = false;
    if (!attr_done) {   // first call is the (uncaptured) correctness run
        cudaFuncSetAttribute(y_kernel,
                             cudaFuncAttributeMaxDynamicSharedMemorySize, GEMM_SMEM);
        cudaFuncSetAttribute(hidg_kernel,
                             cudaFuncAttributeMaxDynamicSharedMemorySize, GEMM_SMEM);
        attr_done = true;
    }

    edge_kernel<<<NN + 512 + 128, 256>>>(adj, xdeg, ydeg, Wm1, bm1, Wm2, bm2,
                                         x, Wg1, Wl2);
    y_kernel<<<dim3(1, NN / 64, YSPL), 256, GEMM_SMEM>>>();
    colsum_kernel<<<dim3(2, 256), 256>>>();
    ycomb_kernel<<<128, 256>>>();
    hidg_kernel<<<dim3(1, NN / 64, HSPL), 256, GEMM_SMEM>>>();
    hid_finish_kernel<<<NN / 16, 256>>>(bl2, Wg2, hid);
    out_kernel<<<NN / 8, 256>>>(out);
}

// round 13
// speedup vs baseline: 1.1079x; 1.1079x over previous
#include <cuda_runtime.h>
#include <cstdint>

#define NN 2048
#define IN_DIM 1024
#define MLPW 16
#define HIDD 256
#define L2DIM 64
#define NCLS 4
#define NSPL 4

// ---------------- scratch (device globals; no allocation) ----------------
__device__ float g_A[(size_t)NN * NN];          // A = adj*mask + I (tf32-rounded)
__device__ float g_Xt[(size_t)NN * IN_DIM];     // tf32-rounded x [2048][1024]
__device__ float g_W12t[(size_t)L2DIM * IN_DIM];// tf32 (Wg1@Wl2)^T [64][1024]
__device__ float g_Yt[(size_t)L2DIM * NN];      // tf32 (dc ⊙ x@W12)^T [64][2048]
__device__ float g_Hp[NSPL][(size_t)NN * L2DIM];// A@Y split-K partials (fp32)
__device__ float g_HW[(size_t)NN * NCLS];       // dc-scaled hid@Wg2
__device__ float g_rowsum[NN];
__device__ float g_colsum[NN];

__device__ __forceinline__ float rsqrt_pos(float v) {
    return v > 0.f ? rsqrtf(v) : 0.f;
}
__device__ __forceinline__ uint32_t f2tf32(float f) {
    uint32_t u;
    asm("cvt.rna.tf32.f32 %0, %1;" : "=r"(u) : "f"(f));
    return u;
}

// ---------------- async copy / ldmatrix helpers ----------------------------
__device__ __forceinline__ void cp_async16(uint32_t smem, const void* gptr) {
    asm volatile("cp.async.cg.shared.global [%0], [%1], 16;\n" ::"r"(smem), "l"(gptr));
}
__device__ __forceinline__ void cp_commit() {
    asm volatile("cp.async.commit_group;\n");
}
template <int N>
__device__ __forceinline__ void cp_wait() {
    asm volatile("cp.async.wait_group %0;\n" ::"n"(N));
}
__device__ __forceinline__ void ldsm4(uint32_t* r, uint32_t addr) {
    asm volatile("ldmatrix.sync.aligned.m8n8.x4.shared.b16 {%0,%1,%2,%3}, [%4];"
                 : "=r"(r[0]), "=r"(r[1]), "=r"(r[2]), "=r"(r[3]) : "r"(addr));
}
__device__ __forceinline__ void mma_tf32(float* c,
                                         const uint32_t* a,
                                         uint32_t b0, uint32_t b1) {
    asm volatile(
        "mma.sync.aligned.m16n8k8.row.col.f32.tf32.tf32.f32 "
        "{%0,%1,%2,%3}, {%4,%5,%6,%7}, {%8,%9}, {%0,%1,%2,%3};"
        : "+f"(c[0]), "+f"(c[1]), "+f"(c[2]), "+f"(c[3])
        : "r"(a[0]), "r"(a[1]), "r"(a[2]), "r"(a[3]), "r"(b0), "r"(b1));
}

// ---------------- kernel 1: edge MLP (rows) + round x + W12t ---------------
// blocks 0..2047: one A-row each (R7-proven form), zero colsum[i]
// blocks 2048..2559: tf32-round x
// blocks 2560..2687: W12t[c][r] = tf32(sum_k Wg1[r][k]*Wl2[k][c]), 8 rows/blk
__global__ __launch_bounds__(256) void edge_kernel(
    const float* __restrict__ adj, const float* __restrict__ xdeg,
    const float* __restrict__ ydeg, const float* __restrict__ Wm1,
    const float* __restrict__ bm1, const float* __restrict__ Wm2,
    const float* __restrict__ bm2, const float* __restrict__ x,
    const float* __restrict__ Wg1, const float* __restrict__ Wl2) {
    int b = blockIdx.x;
    int tid = threadIdx.x;
    if (b < NN) {
        __shared__ float sW1[48], sb1[16], sdw[16], sb2[2];
        if (tid < 48) sW1[tid] = Wm1[tid];
        if (tid < 16) sb1[tid] = bm1[tid];
        if (tid < 16) sdw[tid] = Wm2[2 * tid + 1] - Wm2[2 * tid];
        if (tid < 2)  sb2[tid] = bm2[tid];
        int i = b;
        if (tid == 0) g_colsum[i] = 0.f;   // colsum_kernel runs strictly after
        __syncthreads();

        const float* arow = adj  + (size_t)i * NN;
        const float* xrow = xdeg + (size_t)i * NN;
        const float* yrow = ydeg + (size_t)i * NN;
        float* Arow = g_A + (size_t)i * NN;
        const float db = sb2[1] - sb2[0];

        float rsum = 0.f;
#pragma unroll
        for (int t = 0; t < NN / 256; t++) {
            int j = tid + t * 256;
            float a = arow[j], xd = xrow[j], yd = yrow[j];
            float dl = db;
#pragma unroll
            for (int k = 0; k < MLPW; k++) {
                float h = fmaf(a, sW1[k], fmaf(xd, sW1[16 + k], fmaf(yd, sW1[32 + k], sb1[k])));
                h = fmaxf(h, 0.f);
                dl = fmaf(h, sdw[k], dl);
            }
            float d = 0.5f * dl;
            float th;
            asm("tanh.approx.f32 %0, %1;" : "=f"(th) : "f"(d));
            float mask = fmaf(0.5f, th, 0.5f);
            float Av = a * mask + (j == i ? 1.f : 0.f);
            Av = __uint_as_float(f2tf32(Av));
            Arow[j] = Av;
            rsum += Av;
        }
        for (int off = 16; off; off >>= 1) rsum += __shfl_down_sync(0xffffffffu, rsum, off);
        __shared__ float red[8];
        if ((tid & 31) == 0) red[tid >> 5] = rsum;
        __syncthreads();
        if (tid == 0) {
            float s = 0.f;
#pragma unroll
            for (int w = 0; w < 8; w++) s += red[w];
            g_rowsum[i] = s;
        }
    } else if (b < NN + 512) {
        size_t idx4 = (size_t)(b - NN) * 1024 + tid;
        const float4* src = reinterpret_cast<const float4*>(x);
        float4* dst = reinterpret_cast<float4*>(g_Xt);
#pragma unroll
        for (int t = 0; t < 4; t++) {
            float4 v = src[idx4 + t * 256];
            uint4 u;
            u.x = f2tf32(v.x); u.y = f2tf32(v.y); u.z = f2tf32(v.z); u.w = f2tf32(v.w);
            dst[idx4 + t * 256] = *reinterpret_cast<float4*>(&u);
        }
    } else {
        // W12t: 128 blocks, each computes rows [rbase, rbase+8) of W12 for all 64 cols
        __shared__ float sW[8][256];
        int rbase = (b - NN - 512) * 8;
#pragma unroll
        for (int t = 0; t < 8; t++) {
            int idx = t * 256 + tid;
            sW[idx >> 8][idx & 255] = Wg1[(size_t)(rbase + (idx >> 8)) * HIDD + (idx & 255)];
        }
        __syncthreads();
        int c = tid & 63, rr = tid >> 6;   // rr 0..3
#pragma unroll
        for (int half = 0; half < 2; half++) {
            int rl = rr + half * 4;
            float acc = 0.f;
#pragma unroll 4
            for (int k = 0; k < HIDD; k++)
                acc = fmaf(sW[rl][k], __ldg(&Wl2[k * L2DIM + c]), acc);
            g_W12t[(size_t)c * IN_DIM + rbase + rl] = __uint_as_float(f2tf32(acc));
        }
    }
}

// ---------------- colsum: 512 CTAs, 8 rows each ----------------------------
__global__ __launch_bounds__(256) void colsum_kernel() {
    int j4 = blockIdx.x * 256 + threadIdx.x;     // 0..511 (float4 col)
    int r0 = blockIdx.y * 8;
    const float4* A4 = reinterpret_cast<const float4*>(g_A);
    float sx = 0.f, sy = 0.f, sz = 0.f, sw = 0.f;
#pragma unroll
    for (int i = 0; i < 8; i++) {
        float4 v = A4[(size_t)(r0 + i) * (NN / 4) + j4];
        sx += v.x; sy += v.y; sz += v.z; sw += v.w;
    }
    int j = j4 * 4;
    atomicAdd(&g_colsum[j + 0], sx);
    atomicAdd(&g_colsum[j + 1], sy);
    atomicAdd(&g_colsum[j + 2], sz);
    atomicAdd(&g_colsum[j + 3], sw);
}

// ---------------- tf32 tensor-core GEMM, BK=64, 2-stage, split-K CTAs -----
#define BKK 64
#define HSB 8192      // half-stage bytes per operand (64 rows * 128B)
#define OPB 16384     // per-stage per-operand bytes
#define GEMM_SMEM 65536

template <bool TRANSOUT, int NSPLIT, bool SCALE, int CSTRIDE>
__device__ __forceinline__ void gemm_body(const float* __restrict__ A,
                                          const float* __restrict__ Bt,
                                          float* __restrict__ C, int Kd,
                                          const float* __restrict__ sumvec) {
    extern __shared__ __align__(16) uint8_t smem_dyn[];
    const uint32_t sAu = (uint32_t)__cvta_generic_to_shared(smem_dyn);
    const uint32_t sBu = sAu + 2 * OPB;

    const int tid = threadIdx.x;
    const int lane = tid & 31, warp = tid >> 5;
    const int wm = warp & 1, wn = (warp >> 1) & 1, kg = warp >> 2;  // kg 0..1
    const int gid = lane >> 2, tig = lane & 3;
    const int mi = lane >> 3, lr = lane & 7;
    const int bm0 = blockIdx.y * 64, bn0 = blockIdx.x * 64;
    const int kbase = (NSPLIT > 1) ? blockIdx.z * (Kd / NSPLIT) : 0;

    const int ld_row = tid >> 2;           // 0..63
    const int qb = (tid & 3) << 1;         // 0,2,4,6
    const uint32_t off0 = ld_row * 128 + (((qb + 0) ^ (ld_row & 7)) << 4);
    const uint32_t off1 = ld_row * 128 + (((qb + 1) ^ (ld_row & 7)) << 4);
    const float* Ag = A + (size_t)(bm0 + ld_row) * Kd + kbase;
    const float* Bg = Bt + (size_t)(bn0 + ld_row) * Kd + kbase;

    const int arow = wm * 32 + ((mi & 1) << 3) + lr;
    const int brow = wn * 32 + ((mi >> 1) << 3) + lr;
    const uint32_t axr = arow & 7, bxr = brow & 7;
    const uint32_t qselA = mi >> 1, qselB = mi & 1;
    const uint32_t aOff0 = arow * 128, aOff1 = aOff0 + 16 * 128;
    const uint32_t bOff0 = brow * 128, bOff1 = bOff0 + 16 * 128;
    const uint32_t aqj[2] = {(((uint32_t)(kg * 2 + 0) * 2 + qselA) ^ axr) << 4,
                             (((uint32_t)(kg * 2 + 1) * 2 + qselA) ^ axr) << 4};
    const uint32_t bqj[2] = {(((uint32_t)(kg * 2 + 0) * 2 + qselB) ^ bxr) << 4,
                             (((uint32_t)(kg * 2 + 1) * 2 + qselB) ^ bxr) << 4};

    auto issue = [&](int kt, int s) {
#pragma unroll
        for (int h = 0; h < 2; h++) {
            const float* ag = Ag + (size_t)kt * BKK + h * 32;
            const float* bg = Bg + (size_t)kt * BKK + h * 32;
            uint32_t da = sAu + s * OPB + h * HSB;
            uint32_t db = sBu + s * OPB + h * HSB;
            cp_async16(da + off0, ag + qb * 4);
            cp_async16(da + off1, ag + qb * 4 + 4);
            cp_async16(db + off0, bg + qb * 4);
            cp_async16(db + off1, bg + qb * 4 + 4);
        }
    };

    const int niter = (Kd / NSPLIT) / BKK;
    issue(0, 0);
    cp_commit();

    float acc[2][4][4] = {};

    for (int i = 0; i < niter; i++) {
        cp_wait<0>();
        __syncthreads();
        if (i + 1 < niter) { issue(i + 1, (i + 1) & 1); cp_commit(); }
        const int s = i & 1;
#pragma unroll
        for (int h = 0; h < 2; h++) {
            const uint32_t sAs = sAu + s * OPB + h * HSB;
            const uint32_t sBs = sBu + s * OPB + h * HSB;
#pragma unroll
            for (int jj = 0; jj < 2; jj++) {
                uint32_t af0[4], af1[4], bf0[4], bf1[4];
                ldsm4(af0, sAs + aOff0 + aqj[jj]);
                ldsm4(af1, sAs + aOff1 + aqj[jj]);
                ldsm4(bf0, sBs + bOff0 + bqj[jj]);
                ldsm4(bf1, sBs + bOff1 + bqj[jj]);
                mma_tf32(acc[0][0], af0, bf0[0], bf0[1]);
                mma_tf32(acc[0][1], af0, bf0[2], bf0[3]);
                mma_tf32(acc[0][2], af0, bf1[0], bf1[1]);
                mma_tf32(acc[0][3], af0, bf1[2], bf1[3]);
                mma_tf32(acc[1][0], af1, bf0[0], bf0[1]);
                mma_tf32(acc[1][1], af1, bf0[2], bf0[3]);
                mma_tf32(acc[1][2], af1, bf1[0], bf1[1]);
                mma_tf32(acc[1][3], af1, bf1[2], bf1[3]);
            }
        }
    }

    // ---- 2-way K-split reduction through smem -----------------------------
    __syncthreads();
    float* sred = reinterpret_cast<float*>(smem_dyn);
    const int pi = wm * 2 + wn;
    if (kg == 1) {
#pragma unroll
        for (int mt = 0; mt < 2; mt++)
#pragma unroll
            for (int nt = 0; nt < 4; nt++) {
                int r = mt * 16 + gid, c = nt * 8 + 2 * tig;
                float* base = sred + pi * 1056;
                base[r * 33 + c] = acc[mt][nt][0];
                base[r * 33 + c + 1] = acc[mt][nt][1];
                base[(r + 8) * 33 + c] = acc[mt][nt][2];
                base[(r + 8) * 33 + c + 1] = acc[mt][nt][3];
            }
    }
    __syncthreads();
    if (kg == 0) {
#pragma unroll
        for (int mt = 0; mt < 2; mt++) {
            int r = mt * 16 + gid;
            const float* base = sred + pi * 1056;
            int gr0 = bm0 + wm * 32 + r;
            int gr1 = gr0 + 8;
            float s0 = SCALE ? rsqrt_pos(sumvec[gr0]) : 1.f;
            float s1 = SCALE ? rsqrt_pos(sumvec[gr1]) : 1.f;
#pragma unroll
            for (int nt = 0; nt < 4; nt++) {
                int c = nt * 8 + 2 * tig;
                float v00 = (acc[mt][nt][0] + base[r * 33 + c]) * s0;
                float v01 = (acc[mt][nt][1] + base[r * 33 + c + 1]) * s0;
                float v10 = (acc[mt][nt][2] + base[(r + 8) * 33 + c]) * s1;
                float v11 = (acc[mt][nt][3] + base[(r + 8) * 33 + c + 1]) * s1;
                if (TRANSOUT) {
                    int n0 = bn0 + wn * 32 + c;
                    C[(size_t)n0 * NN + gr0] = __uint_as_float(f2tf32(v00));
                    C[(size_t)(n0 + 1) * NN + gr0] = __uint_as_float(f2tf32(v01));
                    C[(size_t)n0 * NN + gr1] = __uint_as_float(f2tf32(v10));
                    C[(size_t)(n0 + 1) * NN + gr1] = __uint_as_float(f2tf32(v11));
                } else {
                    int col = bn0 + wn * 32 + c;
                    *reinterpret_cast<float2*>(&C[(size_t)gr0 * CSTRIDE + col]) =
                        make_float2(v00, v01);
                    *reinterpret_cast<float2*>(&C[(size_t)gr1 * CSTRIDE + col]) =
                        make_float2(v10, v11);
                }
            }
        }
    }
}

// Y: g_Yt = (dc ⊙ (x @ W12))^T [64][2048], tf32; M=2048 N=64 K=1024
__global__ __launch_bounds__(256) void y_kernel() {
    gemm_body<true, 1, true, 0>(g_Xt, g_W12t, g_Yt, IN_DIM, g_colsum);
}
// HID-GEMM: g_Hp[z] = (g_A @ Y) partial over K-quarter z; M=2048 N=64 K=2048
__global__ __launch_bounds__(256) void hidg_kernel() {
    gemm_body<false, NSPL, false, L2DIM>(g_A, g_Yt, g_Hp[blockIdx.z], NN, nullptr);
}

// ---------------- finish: hid = dr*sum_z Hp + bl2;  HW = dc*(hid@Wg2) ------
__global__ __launch_bounds__(256) void hid_finish_kernel(const float* __restrict__ bl2,
                                                         const float* __restrict__ Wg2,
                                                         float* __restrict__ hid_out) {
    __shared__ float sHid[16][L2DIM + 1];
    int tid = threadIdx.x;
    int rowbase = blockIdx.x * 16;

    int c = tid & 63;
    int rq = tid >> 6;   // 0..3
    float b = bl2[c];
#pragma unroll
    for (int it = 0; it < 4; it++) {
        int row = it * 4 + rq;
        size_t idx = (size_t)(rowbase + row) * L2DIM + c;
        float v = 0.f;
#pragma unroll
        for (int z = 0; z < NSPL; z++) v += g_Hp[z][idx];
        v = v * rsqrt_pos(g_rowsum[rowbase + row]) + b;
        hid_out[idx] = v;
        sHid[row][c] = v;
    }
    __syncthreads();
    if (tid < 64) {
        int r = tid >> 2, cls = tid & 3;
        float s = 0.f;
#pragma unroll
        for (int k = 0; k < L2DIM; k++) s = fmaf(sHid[r][k], Wg2[k * NCLS + cls], s);
        g_HW[(size_t)(rowbase + r) * NCLS + cls] = s * rsqrt_pos(g_colsum[rowbase + r]);
    }
}

// ---------------- out[i] = dr[i] * sum_j A[i,j] * HW[j] --------------------
__global__ __launch_bounds__(256) void out_kernel(float* __restrict__ out) {
    int tid = threadIdx.x;
    __shared__ float sHWt[NCLS][NN];
    const float4* hw4 = reinterpret_cast<const float4*>(g_HW);
#pragma unroll
    for (int t = 0; t < NN / 256; t++) {
        int j = tid + t * 256;
        float4 h = hw4[j];            // HW row j: 4 classes
        sHWt[0][j] = h.x; sHWt[1][j] = h.y; sHWt[2][j] = h.z; sHWt[3][j] = h.w;
    }
    __syncthreads();

    const float4* A4 = reinterpret_cast<const float4*>(g_A);
    __shared__ float red[8][4];
    for (int r = 0; r < 8; r++) {
        int i = blockIdx.x * 8 + r;
        float ax = 0.f, ay = 0.f, az = 0.f, aw = 0.f;
#pragma unroll
        for (int t = 0; t < NN / 1024; t++) {
            int j4 = tid + t * 256;
            float4 a = A4[(size_t)i * (NN / 4) + j4];
            const float4 h0 = *reinterpret_cast<const float4*>(&sHWt[0][j4 * 4]);
            const float4 h1 = *reinterpret_cast<const float4*>(&sHWt[1][j4 * 4]);
            const float4 h2 = *reinterpret_cast<const float4*>(&sHWt[2][j4 * 4]);
            const float4 h3 = *reinterpret_cast<const float4*>(&sHWt[3][j4 * 4]);
            ax += a.x * h0.x + a.y * h0.y + a.z * h0.z + a.w * h0.w;
            ay += a.x * h1.x + a.y * h1.y + a.z * h1.z + a.w * h1.w;
            az += a.x * h2.x + a.y * h2.y + a.z * h2.z + a.w * h2.w;
            aw += a.x * h3.x + a.y * h3.y + a.z * h3.z + a.w * h3.w;
        }
        for (int off = 16; off; off >>= 1) {
            ax += __shfl_down_sync(0xffffffffu, ax, off);
            ay += __shfl_down_sync(0xffffffffu, ay, off);
            az += __shfl_down_sync(0xffffffffu, az, off);
            aw += __shfl_down_sync(0xffffffffu, aw, off);
        }
        if ((tid & 31) == 0) {
            int w = tid >> 5;
            red[w][0] = ax; red[w][1] = ay; red[w][2] = az; red[w][3] = aw;
        }
        __syncthreads();
        if (tid < 4) {
            float s = 0.f;
#pragma unroll
            for (int w = 0; w < 8; w++) s += red[w][tid];
            out[i * NCLS + tid] = rsqrt_pos(g_rowsum[i]) * s;
        }
        __syncthreads();
    }
}

// ---------------- launch (single stream, 6 kernels) ------------------------
extern "C" void kernel_launch(void* const* d_in, const int* in_sizes, int n_in,
                              void* d_out, int out_size) {
    const float* x    = (const float*)d_in[0];
    const float* adj  = (const float*)d_in[1];
    const float* xdeg = (const float*)d_in[2];
    const float* ydeg = (const float*)d_in[3];
    const float* Wm1  = (const float*)d_in[4];
    const float* bm1  = (const float*)d_in[5];
    const float* Wm2  = (const float*)d_in[6];
    const float* bm2  = (const float*)d_in[7];
    const float* Wg1  = (const float*)d_in[8];
    const float* Wl2  = (const float*)d_in[9];
    const float* bl2  = (const float*)d_in[10];
    const float* Wg2  = (const float*)d_in[11];

    float* out = (float*)d_out;               // [2048, 4]
    float* hid = out + (size_t)NN * NCLS;     // [2048, 64]

    static bool attr_done = false;
    if (!attr_done) {   // first call is the (uncaptured) correctness run
        cudaFuncSetAttribute(y_kernel,
                             cudaFuncAttributeMaxDynamicSharedMemorySize, GEMM_SMEM);
        cudaFuncSetAttribute(hidg_kernel,
                             cudaFuncAttributeMaxDynamicSharedMemorySize, GEMM_SMEM);
        attr_done = true;
    }

    edge_kernel<<<NN + 512 + 128, 256>>>(adj, xdeg, ydeg, Wm1, bm1, Wm2, bm2,
                                         x, Wg1, Wl2);
    colsum_kernel<<<dim3(2, 256), 256>>>();
    y_kernel<<<dim3(1, NN / 64, 1), 256, GEMM_SMEM>>>();
    hidg_kernel<<<dim3(1, NN / 64, NSPL), 256, GEMM_SMEM>>>();
    hid_finish_kernel<<<NN / 16, 256>>>(bl2, Wg2, hid);
    out_kernel<<<NN / 8, 256>>>(out);
}

// round 14
// speedup vs baseline: 1.1660x; 1.0525x over previous
#include <cuda_runtime.h>
#include <cuda.h>
#include <cstdint>

#define NN 2048
#define IN_DIM 1024
#define MLPW 16
#define HIDD 256
#define L2DIM 64
#define NCLS 4
#define NSPL 4

// ---------------- scratch (device globals; no allocation) ----------------
__device__ float g_A[(size_t)NN * NN];          // A = adj*mask + I (tf32-rounded)
__device__ float g_Xt[(size_t)NN * IN_DIM];     // tf32-rounded x [2048][1024]
__device__ float g_W12t[(size_t)L2DIM * IN_DIM];// tf32 (Wg1@Wl2)^T [64][1024]
__device__ float g_Yt[(size_t)L2DIM * NN];      // tf32 (dc ⊙ x@W12)^T [64][2048]
__device__ float g_Hp[NSPL][(size_t)NN * L2DIM];// A@Y split-K partials (fp32)
__device__ float g_HW[(size_t)NN * NCLS];       // dc-scaled hid@Wg2
__device__ float g_rowsum[NN];
__device__ float g_colsum[NN];

__device__ __forceinline__ float rsqrt_pos(float v) {
    return v > 0.f ? rsqrtf(v) : 0.f;
}
__device__ __forceinline__ uint32_t f2tf32(float f) {
    uint32_t u;
    asm("cvt.rna.tf32.f32 %0, %1;" : "=r"(u) : "f"(f));
    return u;
}

// ---------------- TMA / mbarrier / ldmatrix helpers ------------------------
__device__ __forceinline__ void tma2d(uint32_t dst, const CUtensorMap* m,
                                      int x, int y, uint32_t bar) {
    asm volatile(
        "cp.async.bulk.tensor.2d.shared::cta.global.tile.mbarrier::complete_tx::bytes "
        "[%0], [%1, {%2, %3}], [%4];"
        :: "r"(dst), "l"(m), "r"(x), "r"(y), "r"(bar) : "memory");
}
__device__ __forceinline__ void mbar_init(uint32_t bar, uint32_t cnt) {
    asm volatile("mbarrier.init.shared.b64 [%0], %1;" :: "r"(bar), "r"(cnt) : "memory");
}
__device__ __forceinline__ void mbar_expect_tx(uint32_t bar, uint32_t bytes) {
    asm volatile("mbarrier.arrive.expect_tx.shared.b64 _, [%0], %1;"
                 :: "r"(bar), "r"(bytes) : "memory");
}
__device__ __forceinline__ void mbar_wait(uint32_t bar, uint32_t parity) {
    uint32_t done;
    asm volatile(
        "{\n\t.reg .pred p;\n\t"
        "mbarrier.try_wait.parity.acquire.cta.shared::cta.b64 p, [%1], %2;\n\t"
        "selp.b32 %0, 1, 0, p;\n\t}"
        : "=r"(done) : "r"(bar), "r"(parity) : "memory");
    if (!done) {
        asm volatile(
            "{\n\t.reg .pred P1;\n\t"
            "WL_%=:\n\t"
            "mbarrier.try_wait.parity.acquire.cta.shared::cta.b64 P1, [%0], %1, 0x989680;\n\t"
            "@P1 bra.uni WD_%=;\n\t"
            "bra.uni WL_%=;\n\t"
            "WD_%=:\n\t}"
            :: "r"(bar), "r"(parity) : "memory");
    }
}
__device__ __forceinline__ void ldsm4(uint32_t* r, uint32_t addr) {
    asm volatile("ldmatrix.sync.aligned.m8n8.x4.shared.b16 {%0,%1,%2,%3}, [%4];"
                 : "=r"(r[0]), "=r"(r[1]), "=r"(r[2]), "=r"(r[3]) : "r"(addr));
}
__device__ __forceinline__ void mma_tf32(float* c,
                                         const uint32_t* a,
                                         uint32_t b0, uint32_t b1) {
    asm volatile(
        "mma.sync.aligned.m16n8k8.row.col.f32.tf32.tf32.f32 "
        "{%0,%1,%2,%3}, {%4,%5,%6,%7}, {%8,%9}, {%0,%1,%2,%3};"
        : "+f"(c[0]), "+f"(c[1]), "+f"(c[2]), "+f"(c[3])
        : "r"(a[0]), "r"(a[1]), "r"(a[2]), "r"(a[3]), "r"(b0), "r"(b1));
}

// ---------------- kernel 1: edge MLP (rows) + round x + W12t ---------------
__global__ __launch_bounds__(256) void edge_kernel(
    const float* __restrict__ adj, const float* __restrict__ xdeg,
    const float* __restrict__ ydeg, const float* __restrict__ Wm1,
    const float* __restrict__ bm1, const float* __restrict__ Wm2,
    const float* __restrict__ bm2, const float* __restrict__ x,
    const float* __restrict__ Wg1, const float* __restrict__ Wl2) {
    int b = blockIdx.x;
    int tid = threadIdx.x;
    if (b < NN) {
        __shared__ float sW1[48], sb1[16], sdw[16], sb2[2];
        if (tid < 48) sW1[tid] = Wm1[tid];
        if (tid < 16) sb1[tid] = bm1[tid];
        if (tid < 16) sdw[tid] = Wm2[2 * tid + 1] - Wm2[2 * tid];
        if (tid < 2)  sb2[tid] = bm2[tid];
        int i = b;
        if (tid == 0) g_colsum[i] = 0.f;   // colsum_kernel runs strictly after
        __syncthreads();

        const float* arow = adj  + (size_t)i * NN;
        const float* xrow = xdeg + (size_t)i * NN;
        const float* yrow = ydeg + (size_t)i * NN;
        float* Arow = g_A + (size_t)i * NN;
        const float db = sb2[1] - sb2[0];

        float rsum = 0.f;
#pragma unroll
        for (int t = 0; t < NN / 256; t++) {
            int j = tid + t * 256;
            float a = arow[j], xd = xrow[j], yd = yrow[j];
            float dl = db;
#pragma unroll
            for (int k = 0; k < MLPW; k++) {
                float h = fmaf(a, sW1[k], fmaf(xd, sW1[16 + k], fmaf(yd, sW1[32 + k], sb1[k])));
                h = fmaxf(h, 0.f);
                dl = fmaf(h, sdw[k], dl);
            }
            float d = 0.5f * dl;
            float th;
            asm("tanh.approx.f32 %0, %1;" : "=f"(th) : "f"(d));
            float mask = fmaf(0.5f, th, 0.5f);
            float Av = a * mask + (j == i ? 1.f : 0.f);
            Av = __uint_as_float(f2tf32(Av));
            Arow[j] = Av;
            rsum += Av;
        }
        for (int off = 16; off; off >>= 1) rsum += __shfl_down_sync(0xffffffffu, rsum, off);
        __shared__ float red[8];
        if ((tid & 31) == 0) red[tid >> 5] = rsum;
        __syncthreads();
        if (tid == 0) {
            float s = 0.f;
#pragma unroll
            for (int w = 0; w < 8; w++) s += red[w];
            g_rowsum[i] = s;
        }
    } else if (b < NN + 512) {
        size_t idx4 = (size_t)(b - NN) * 1024 + tid;
        const float4* src = reinterpret_cast<const float4*>(x);
        float4* dst = reinterpret_cast<float4*>(g_Xt);
#pragma unroll
        for (int t = 0; t < 4; t++) {
            float4 v = src[idx4 + t * 256];
            uint4 u;
            u.x = f2tf32(v.x); u.y = f2tf32(v.y); u.z = f2tf32(v.z); u.w = f2tf32(v.w);
            dst[idx4 + t * 256] = *reinterpret_cast<float4*>(&u);
        }
    } else {
        // W12t: 128 blocks, each computes rows [rbase, rbase+8) of W12 for all 64 cols
        __shared__ float sW[8][256];
        int rbase = (b - NN - 512) * 8;
#pragma unroll
        for (int t = 0; t < 8; t++) {
            int idx = t * 256 + tid;
            sW[idx >> 8][idx & 255] = Wg1[(size_t)(rbase + (idx >> 8)) * HIDD + (idx & 255)];
        }
        __syncthreads();
        int c = tid & 63, rr = tid >> 6;   // rr 0..3
#pragma unroll
        for (int half = 0; half < 2; half++) {
            int rl = rr + half * 4;
            float acc = 0.f;
#pragma unroll 4
            for (int k = 0; k < HIDD; k++)
                acc = fmaf(sW[rl][k], __ldg(&Wl2[k * L2DIM + c]), acc);
            g_W12t[(size_t)c * IN_DIM + rbase + rl] = __uint_as_float(f2tf32(acc));
        }
    }
}

// ---------------- colsum: 512 CTAs, 8 rows each ----------------------------
__global__ __launch_bounds__(256) void colsum_kernel() {
    int j4 = blockIdx.x * 256 + threadIdx.x;     // 0..511 (float4 col)
    int r0 = blockIdx.y * 8;
    const float4* A4 = reinterpret_cast<const float4*>(g_A);
    float sx = 0.f, sy = 0.f, sz = 0.f, sw = 0.f;
#pragma unroll
    for (int i = 0; i < 8; i++) {
        float4 v = A4[(size_t)(r0 + i) * (NN / 4) + j4];
        sx += v.x; sy += v.y; sz += v.z; sw += v.w;
    }
    int j = j4 * 4;
    atomicAdd(&g_colsum[j + 0], sx);
    atomicAdd(&g_colsum[j + 1], sy);
    atomicAdd(&g_colsum[j + 2], sz);
    atomicAdd(&g_colsum[j + 3], sw);
}

// ---------------- tf32 tensor-core GEMM, TMA loader, BK=64, 2-stage --------
#define BKK 64
#define HSB 8192      // half-stage bytes per operand (64 rows * 128B)
#define OPB 16384     // per-stage per-operand bytes
#define STG_TX 32768  // bytes per full stage (A 16KB + B 16KB)
#define GEMM_SMEM (1024 + 1024 + 4 * OPB)   // align pad + mbarriers + stages

template <bool TRANSOUT, int NSPLIT, bool SCALE, int CSTRIDE>
__device__ __forceinline__ void gemm_body(const CUtensorMap* mapA,
                                          const CUtensorMap* mapB,
                                          float* __restrict__ C, int Kd,
                                          const float* __restrict__ sumvec) {
    extern __shared__ __align__(16) uint8_t smem_dyn[];
    const uint32_t raw = (uint32_t)__cvta_generic_to_shared(smem_dyn);
    const uint32_t base0 = (raw + 1023u) & ~1023u;   // 1024-aligned for SW128
    const uint32_t barB = base0;                      // two mbarriers
    const uint32_t sAu = base0 + 1024;
    const uint32_t sBu = sAu + 2 * OPB;

    const int tid = threadIdx.x;
    const int lane = tid & 31, warp = tid >> 5;
    const int wm = warp & 1, wn = (warp >> 1) & 1, kg = warp >> 2;  // kg 0..1
    const int gid = lane >> 2, tig = lane & 3;
    const int mi = lane >> 3, lr = lane & 7;
    const int bm0 = blockIdx.y * 64, bn0 = blockIdx.x * 64;
    const int kbase = (NSPLIT > 1) ? blockIdx.z * (Kd / NSPLIT) : 0;

    const int arow = wm * 32 + ((mi & 1) << 3) + lr;
    const int brow = wn * 32 + ((mi >> 1) << 3) + lr;
    const uint32_t axr = arow & 7, bxr = brow & 7;
    const uint32_t qselA = mi >> 1, qselB = mi & 1;
    const uint32_t aOff0 = arow * 128, aOff1 = aOff0 + 16 * 128;
    const uint32_t bOff0 = brow * 128, bOff1 = bOff0 + 16 * 128;
    const uint32_t aqj[2] = {(((uint32_t)(kg * 2 + 0) * 2 + qselA) ^ axr) << 4,
                             (((uint32_t)(kg * 2 + 1) * 2 + qselA) ^ axr) << 4};
    const uint32_t bqj[2] = {(((uint32_t)(kg * 2 + 0) * 2 + qselB) ^ bxr) << 4,
                             (((uint32_t)(kg * 2 + 1) * 2 + qselB) ^ bxr) << 4};

    if (tid == 0) {
        mbar_init(barB, 1);
        mbar_init(barB + 8, 1);
        asm volatile("fence.proxy.async.shared::cta;" ::: "memory");
    }
    __syncthreads();

    auto issue = [&](int kt, int s) {   // tid==0 only
        uint32_t bar = barB + s * 8;
        mbar_expect_tx(bar, STG_TX);
        int k0 = kbase + kt * BKK;
        tma2d(sAu + s * OPB,       mapA, k0,      bm0, bar);
        tma2d(sAu + s * OPB + HSB, mapA, k0 + 32, bm0, bar);
        tma2d(sBu + s * OPB,       mapB, k0,      bn0, bar);
        tma2d(sBu + s * OPB + HSB, mapB, k0 + 32, bn0, bar);
    };

    const int niter = (Kd / NSPLIT) / BKK;
    if (tid == 0) {
        issue(0, 0);
        if (niter > 1) issue(1, 1);
    }

    float acc[2][4][4] = {};
    uint32_t phase0 = 0, phase1 = 0;

    for (int i = 0; i < niter; i++) {
        const int s = i & 1;
        if (s == 0) { mbar_wait(barB, phase0); phase0 ^= 1; }
        else        { mbar_wait(barB + 8, phase1); phase1 ^= 1; }
#pragma unroll
        for (int h = 0; h < 2; h++) {
            const uint32_t sAs = sAu + s * OPB + h * HSB;
            const uint32_t sBs = sBu + s * OPB + h * HSB;
#pragma unroll
            for (int jj = 0; jj < 2; jj++) {
                uint32_t af0[4], af1[4], bf0[4], bf1[4];
                ldsm4(af0, sAs + aOff0 + aqj[jj]);
                ldsm4(af1, sAs + aOff1 + aqj[jj]);
                ldsm4(bf0, sBs + bOff0 + bqj[jj]);
                ldsm4(bf1, sBs + bOff1 + bqj[jj]);
                mma_tf32(acc[0][0], af0, bf0[0], bf0[1]);
                mma_tf32(acc[0][1], af0, bf0[2], bf0[3]);
                mma_tf32(acc[0][2], af0, bf1[0], bf1[1]);
                mma_tf32(acc[0][3], af0, bf1[2], bf1[3]);
                mma_tf32(acc[1][0], af1, bf0[0], bf0[1]);
                mma_tf32(acc[1][1], af1, bf0[2], bf0[3]);
                mma_tf32(acc[1][2], af1, bf1[0], bf1[1]);
                mma_tf32(acc[1][3], af1, bf1[2], bf1[3]);
            }
        }
        __syncthreads();   // all warps done with stage s before refill
        if (i + 2 < niter && tid == 0) issue(i + 2, s);
    }

    // ---- 2-way K-split reduction through smem (aliases stage region) ------
    float* sred = reinterpret_cast<float*>(smem_dyn + (base0 - raw) + 1024);
    const int pi = wm * 2 + wn;
    if (kg == 1) {
#pragma unroll
        for (int mt = 0; mt < 2; mt++)
#pragma unroll
            for (int nt = 0; nt < 4; nt++) {
                int r = mt * 16 + gid, c = nt * 8 + 2 * tig;
                float* basep = sred + pi * 1056;
                basep[r * 33 + c] = acc[mt][nt][0];
                basep[r * 33 + c + 1] = acc[mt][nt][1];
                basep[(r + 8) * 33 + c] = acc[mt][nt][2];
                basep[(r + 8) * 33 + c + 1] = acc[mt][nt][3];
            }
    }
    __syncthreads();
    if (kg == 0) {
#pragma unroll
        for (int mt = 0; mt < 2; mt++) {
            int r = mt * 16 + gid;
            const float* basep = sred + pi * 1056;
            int gr0 = bm0 + wm * 32 + r;
            int gr1 = gr0 + 8;
            float s0 = SCALE ? rsqrt_pos(sumvec[gr0]) : 1.f;
            float s1 = SCALE ? rsqrt_pos(sumvec[gr1]) : 1.f;
#pragma unroll
            for (int nt = 0; nt < 4; nt++) {
                int c = nt * 8 + 2 * tig;
                float v00 = (acc[mt][nt][0] + basep[r * 33 + c]) * s0;
                float v01 = (acc[mt][nt][1] + basep[r * 33 + c + 1]) * s0;
                float v10 = (acc[mt][nt][2] + basep[(r + 8) * 33 + c]) * s1;
                float v11 = (acc[mt][nt][3] + basep[(r + 8) * 33 + c + 1]) * s1;
                if (TRANSOUT) {
                    int n0 = bn0 + wn * 32 + c;
                    C[(size_t)n0 * NN + gr0] = __uint_as_float(f2tf32(v00));
                    C[(size_t)(n0 + 1) * NN + gr0] = __uint_as_float(f2tf32(v01));
                    C[(size_t)n0 * NN + gr1] = __uint_as_float(f2tf32(v10));
                    C[(size_t)(n0 + 1) * NN + gr1] = __uint_as_float(f2tf32(v11));
                } else {
                    int col = bn0 + wn * 32 + c;
                    *reinterpret_cast<float2*>(&C[(size_t)gr0 * CSTRIDE + col]) =
                        make_float2(v00, v01);
                    *reinterpret_cast<float2*>(&C[(size_t)gr1 * CSTRIDE + col]) =
                        make_float2(v10, v11);
                }
            }
        }
    }
}

// Y: g_Yt = (dc ⊙ (x @ W12))^T [64][2048], tf32; M=2048 N=64 K=1024
__global__ __launch_bounds__(256) void y_kernel(
    const __grid_constant__ CUtensorMap mA, const __grid_constant__ CUtensorMap mB) {
    gemm_body<true, 1, true, 0>(&mA, &mB, g_Yt, IN_DIM, g_colsum);
}
// HID-GEMM: g_Hp[z] = (g_A @ Y) partial over K-quarter z; M=2048 N=64 K=2048
__global__ __launch_bounds__(256) void hidg_kernel(
    const __grid_constant__ CUtensorMap mA, const __grid_constant__ CUtensorMap mB) {
    gemm_body<false, NSPL, false, L2DIM>(&mA, &mB, g_Hp[blockIdx.z], NN, nullptr);
}

// ---------------- finish: hid = dr*sum_z Hp + bl2;  HW = dc*(hid@Wg2) ------
__global__ __launch_bounds__(256) void hid_finish_kernel(const float* __restrict__ bl2,
                                                         const float* __restrict__ Wg2,
                                                         float* __restrict__ hid_out) {
    __shared__ float sHid[16][L2DIM + 1];
    int tid = threadIdx.x;
    int rowbase = blockIdx.x * 16;

    int c = tid & 63;
    int rq = tid >> 6;   // 0..3
    float b = bl2[c];
#pragma unroll
    for (int it = 0; it < 4; it++) {
        int row = it * 4 + rq;
        size_t idx = (size_t)(rowbase + row) * L2DIM + c;
        float v = 0.f;
#pragma unroll
        for (int z = 0; z < NSPL; z++) v += g_Hp[z][idx];
        v = v * rsqrt_pos(g_rowsum[rowbase + row]) + b;
        hid_out[idx] = v;
        sHid[row][c] = v;
    }
    __syncthreads();
    if (tid < 64) {
        int r = tid >> 2, cls = tid & 3;
        float s = 0.f;
#pragma unroll
        for (int k = 0; k < L2DIM; k++) s = fmaf(sHid[r][k], Wg2[k * NCLS + cls], s);
        g_HW[(size_t)(rowbase + r) * NCLS + cls] = s * rsqrt_pos(g_colsum[rowbase + r]);
    }
}

// ---------------- out[i] = dr[i] * sum_j A[i,j] * HW[j] --------------------
__global__ __launch_bounds__(256) void out_kernel(float* __restrict__ out) {
    int tid = threadIdx.x;
    __shared__ float sHWt[NCLS][NN];
    const float4* hw4 = reinterpret_cast<const float4*>(g_HW);
#pragma unroll
    for (int t = 0; t < NN / 256; t++) {
        int j = tid + t * 256;
        float4 h = hw4[j];            // HW row j: 4 classes
        sHWt[0][j] = h.x; sHWt[1][j] = h.y; sHWt[2][j] = h.z; sHWt[3][j] = h.w;
    }
    __syncthreads();

    const float4* A4 = reinterpret_cast<const float4*>(g_A);
    __shared__ float red[8][4];
    for (int r = 0; r < 8; r++) {
        int i = blockIdx.x * 8 + r;
        float ax = 0.f, ay = 0.f, az = 0.f, aw = 0.f;
#pragma unroll
        for (int t = 0; t < NN / 1024; t++) {
            int j4 = tid + t * 256;
            float4 a = A4[(size_t)i * (NN / 4) + j4];
            const float4 h0 = *reinterpret_cast<const float4*>(&sHWt[0][j4 * 4]);
            const float4 h1 = *reinterpret_cast<const float4*>(&sHWt[1][j4 * 4]);
            const float4 h2 = *reinterpret_cast<const float4*>(&sHWt[2][j4 * 4]);
            const float4 h3 = *reinterpret_cast<const float4*>(&sHWt[3][j4 * 4]);
            ax += a.x * h0.x + a.y * h0.y + a.z * h0.z + a.w * h0.w;
            ay += a.x * h1.x + a.y * h1.y + a.z * h1.z + a.w * h1.w;
            az += a.x * h2.x + a.y * h2.y + a.z * h2.z + a.w * h2.w;
            aw += a.x * h3.x + a.y * h3.y + a.z * h3.z + a.w * h3.w;
        }
        for (int off = 16; off; off >>= 1) {
            ax += __shfl_down_sync(0xffffffffu, ax, off);
            ay += __shfl_down_sync(0xffffffffu, ay, off);
            az += __shfl_down_sync(0xffffffffu, az, off);
            aw += __shfl_down_sync(0xffffffffu, aw, off);
        }
        if ((tid & 31) == 0) {
            int w = tid >> 5;
            red[w][0] = ax; red[w][1] = ay; red[w][2] = az; red[w][3] = aw;
        }
        __syncthreads();
        if (tid < 4) {
            float s = 0.f;
#pragma unroll
            for (int w = 0; w < 8; w++) s += red[w][tid];
            out[i * NCLS + tid] = rsqrt_pos(g_rowsum[i]) * s;
        }
        __syncthreads();
    }
}

// ---------------- host: tensor-map setup + launch --------------------------
typedef CUresult (*PFN_tmEncode)(
    CUtensorMap*, CUtensorMapDataType, cuuint32_t, void*,
    const cuuint64_t*, const cuuint64_t*, const cuuint32_t*, const cuuint32_t*,
    CUtensorMapInterleave, CUtensorMapSwizzle, CUtensorMapL2promotion,
    CUtensorMapFloatOOBfill);

extern "C" void kernel_launch(void* const* d_in, const int* in_sizes, int n_in,
                              void* d_out, int out_size) {
    const float* x    = (const float*)d_in[0];
    const float* adj  = (const float*)d_in[1];
    const float* xdeg = (const float*)d_in[2];
    const float* ydeg = (const float*)d_in[3];
    const float* Wm1  = (const float*)d_in[4];
    const float* bm1  = (const float*)d_in[5];
    const float* Wm2  = (const float*)d_in[6];
    const float* bm2  = (const float*)d_in[7];
    const float* Wg1  = (const float*)d_in[8];
    const float* Wl2  = (const float*)d_in[9];
    const float* bl2  = (const float*)d_in[10];
    const float* Wg2  = (const float*)d_in[11];

    float* out = (float*)d_out;               // [2048, 4]
    float* hid = out + (size_t)NN * NCLS;     // [2048, 64]

    static bool init_done = false;
    static CUtensorMap mA_y, mB_y, mA_h, mB_h;
    if (!init_done) {   // first call is the (uncaptured) correctness run
        cudaFuncSetAttribute(y_kernel,
                             cudaFuncAttributeMaxDynamicSharedMemorySize, GEMM_SMEM);
        cudaFuncSetAttribute(hidg_kernel,
                             cudaFuncAttributeMaxDynamicSharedMemorySize, GEMM_SMEM);
        void* fn = nullptr;
        cudaDriverEntryPointQueryResult qr;
        cudaGetDriverEntryPoint("cuTensorMapEncodeTiled", &fn,
                                cudaEnableDefault, &qr);
        PFN_tmEncode enc = (PFN_tmEncode)fn;
        void *pA, *pXt, *pW12t, *pYt;
        cudaGetSymbolAddress(&pA, g_A);
        cudaGetSymbolAddress(&pXt, g_Xt);
        cudaGetSymbolAddress(&pW12t, g_W12t);
        cudaGetSymbolAddress(&pYt, g_Yt);
        auto mk = [&](CUtensorMap* m, void* ptr, uint64_t d0, uint64_t d1) {
            cuuint64_t dims[2] = {d0, d1};
            cuuint64_t strides[1] = {d0 * 4};
            cuuint32_t box[2] = {32, 64};
            cuuint32_t es[2] = {1, 1};
            enc(m, CU_TENSOR_MAP_DATA_TYPE_FLOAT32, 2, ptr, dims, strides, box, es,
                CU_TENSOR_MAP_INTERLEAVE_NONE, CU_TENSOR_MAP_SWIZZLE_128B,
                CU_TENSOR_MAP_L2_PROMOTION_L2_128B,
                CU_TENSOR_MAP_FLOAT_OOB_FILL_NONE);
        };
        mk(&mA_y, pXt, IN_DIM, NN);
        mk(&mB_y, pW12t, IN_DIM, L2DIM);
        mk(&mA_h, pA, NN, NN);
        mk(&mB_h, pYt, NN, L2DIM);
        init_done = true;
    }

    edge_kernel<<<NN + 512 + 128, 256>>>(adj, xdeg, ydeg, Wm1, bm1, Wm2, bm2,
                                         x, Wg1, Wl2);
    colsum_kernel<<<dim3(2, 256), 256>>>();
    y_kernel<<<dim3(1, NN / 64, 1), 256, GEMM_SMEM>>>(mA_y, mB_y);
    hidg_kernel<<<dim3(1, NN / 64, NSPL), 256, GEMM_SMEM>>>(mA_h, mB_h);
    hid_finish_kernel<<<NN / 16, 256>>>(bl2, Wg2, hid);
    out_kernel<<<NN / 8, 256>>>(out);
}

// round 15
// speedup vs baseline: 1.2170x; 1.0437x over previous
#include <cuda_runtime.h>
#include <cuda.h>
#include <cstdint>

#define NN 2048
#define IN_DIM 1024
#define MLPW 16
#define HIDD 256
#define L2DIM 64
#define NCLS 4
#define NSPL 4

// ---------------- scratch (device globals; no allocation) ----------------
__device__ float g_A[(size_t)NN * NN];          // A = adj*mask + I (tf32-rounded)
__device__ float g_Xt[(size_t)NN * IN_DIM];     // tf32-rounded x [2048][1024]
__device__ float g_W12t[(size_t)L2DIM * IN_DIM];// tf32 (Wg1@Wl2)^T [64][1024]
__device__ float g_Yt[(size_t)L2DIM * NN];      // tf32 (dc ⊙ x@W12)^T [64][2048]
__device__ float g_Hp[NSPL][(size_t)NN * L2DIM];// A@Y split-K partials (fp32)
__device__ float g_HW[(size_t)NN * NCLS];       // dc-scaled hid@Wg2
__device__ float g_rowsum[NN];
__device__ float g_colsum[NN];   // zero at load (.bss); re-zeroed by out_kernel

__device__ __forceinline__ float rsqrt_pos(float v) {
    return v > 0.f ? rsqrtf(v) : 0.f;
}
__device__ __forceinline__ uint32_t f2tf32(float f) {
    uint32_t u;
    asm("cvt.rna.tf32.f32 %0, %1;" : "=r"(u) : "f"(f));
    return u;
}

// ---------------- TMA / mbarrier / ldmatrix helpers ------------------------
__device__ __forceinline__ void tma2d(uint32_t dst, const CUtensorMap* m,
                                      int x, int y, uint32_t bar) {
    asm volatile(
        "cp.async.bulk.tensor.2d.shared::cta.global.tile.mbarrier::complete_tx::bytes "
        "[%0], [%1, {%2, %3}], [%4];"
        :: "r"(dst), "l"(m), "r"(x), "r"(y), "r"(bar) : "memory");
}
__device__ __forceinline__ void mbar_init(uint32_t bar, uint32_t cnt) {
    asm volatile("mbarrier.init.shared.b64 [%0], %1;" :: "r"(bar), "r"(cnt) : "memory");
}
__device__ __forceinline__ void mbar_expect_tx(uint32_t bar, uint32_t bytes) {
    asm volatile("mbarrier.arrive.expect_tx.shared.b64 _, [%0], %1;"
                 :: "r"(bar), "r"(bytes) : "memory");
}
__device__ __forceinline__ void mbar_wait(uint32_t bar, uint32_t parity) {
    uint32_t done;
    asm volatile(
        "{\n\t.reg .pred p;\n\t"
        "mbarrier.try_wait.parity.acquire.cta.shared::cta.b64 p, [%1], %2;\n\t"
        "selp.b32 %0, 1, 0, p;\n\t}"
        : "=r"(done) : "r"(bar), "r"(parity) : "memory");
    if (!done) {
        asm volatile(
            "{\n\t.reg .pred P1;\n\t"
            "WL_%=:\n\t"
            "mbarrier.try_wait.parity.acquire.cta.shared::cta.b64 P1, [%0], %1, 0x989680;\n\t"
            "@P1 bra.uni WD_%=;\n\t"
            "bra.uni WL_%=;\n\t"
            "WD_%=:\n\t}"
            :: "r"(bar), "r"(parity) : "memory");
    }
}
__device__ __forceinline__ void ldsm4(uint32_t* r, uint32_t addr) {
    asm volatile("ldmatrix.sync.aligned.m8n8.x4.shared.b16 {%0,%1,%2,%3}, [%4];"
                 : "=r"(r[0]), "=r"(r[1]), "=r"(r[2]), "=r"(r[3]) : "r"(addr));
}
__device__ __forceinline__ void mma_tf32(float* c,
                                         const uint32_t* a,
                                         uint32_t b0, uint32_t b1) {
    asm volatile(
        "mma.sync.aligned.m16n8k8.row.col.f32.tf32.tf32.f32 "
        "{%0,%1,%2,%3}, {%4,%5,%6,%7}, {%8,%9}, {%0,%1,%2,%3};"
        : "+f"(c[0]), "+f"(c[1]), "+f"(c[2]), "+f"(c[3])
        : "r"(a[0]), "r"(a[1]), "r"(a[2]), "r"(a[3]), "r"(b0), "r"(b1));
}

// ---------------- kernel 1: edge MLP + fused colsum + round x + W12t -------
// blocks 0..2047: one A-row each; colsum via register partials + atomics
// blocks 2048..2559: tf32-round x
// blocks 2560..2687: W12t[c][r] = tf32(sum_k Wg1[r][k]*Wl2[k][c]), 8 rows/blk
__global__ __launch_bounds__(256) void edge_kernel(
    const float* __restrict__ adj, const float* __restrict__ xdeg,
    const float* __restrict__ ydeg, const float* __restrict__ Wm1,
    const float* __restrict__ bm1, const float* __restrict__ Wm2,
    const float* __restrict__ bm2, const float* __restrict__ x,
    const float* __restrict__ Wg1, const float* __restrict__ Wl2) {
    int b = blockIdx.x;
    int tid = threadIdx.x;
    if (b < NN) {
        __shared__ float sW1[48], sb1[16], sdw[16], sb2[2];
        if (tid < 48) sW1[tid] = Wm1[tid];
        if (tid < 16) sb1[tid] = bm1[tid];
        if (tid < 16) sdw[tid] = Wm2[2 * tid + 1] - Wm2[2 * tid];
        if (tid < 2)  sb2[tid] = bm2[tid];
        int i = b;
        __syncthreads();

        const float* arow = adj  + (size_t)i * NN;
        const float* xrow = xdeg + (size_t)i * NN;
        const float* yrow = ydeg + (size_t)i * NN;
        float* Arow = g_A + (size_t)i * NN;
        const float db = sb2[1] - sb2[0];

        float rsum = 0.f;
        float csum[8];
#pragma unroll
        for (int t = 0; t < 8; t++) csum[t] = 0.f;
#pragma unroll
        for (int t = 0; t < NN / 256; t++) {
            int j = tid + t * 256;
            float a = arow[j], xd = xrow[j], yd = yrow[j];
            float dl = db;
#pragma unroll
            for (int k = 0; k < MLPW; k++) {
                float h = fmaf(a, sW1[k], fmaf(xd, sW1[16 + k], fmaf(yd, sW1[32 + k], sb1[k])));
                h = fmaxf(h, 0.f);
                dl = fmaf(h, sdw[k], dl);
            }
            float d = 0.5f * dl;
            float th;
            asm("tanh.approx.f32 %0, %1;" : "=f"(th) : "f"(d));
            float mask = fmaf(0.5f, th, 0.5f);
            float Av = a * mask + (j == i ? 1.f : 0.f);
            Av = __uint_as_float(f2tf32(Av));
            Arow[j] = Av;
            rsum += Av;
            csum[t] = Av;   // one column per t-slot for this row
        }
        for (int off = 16; off; off >>= 1) rsum += __shfl_down_sync(0xffffffffu, rsum, off);
        __shared__ float red[8];
        if ((tid & 31) == 0) red[tid >> 5] = rsum;
        __syncthreads();
        if (tid == 0) {
            float s = 0.f;
#pragma unroll
            for (int w = 0; w < 8; w++) s += red[w];
            g_rowsum[i] = s;
        }
        // fused colsum: one atomic per (thread, column slot)
#pragma unroll
        for (int t = 0; t < 8; t++)
            atomicAdd(&g_colsum[tid + t * 256], csum[t]);
    } else if (b < NN + 512) {
        size_t idx4 = (size_t)(b - NN) * 1024 + tid;
        const float4* src = reinterpret_cast<const float4*>(x);
        float4* dst = reinterpret_cast<float4*>(g_Xt);
#pragma unroll
        for (int t = 0; t < 4; t++) {
            float4 v = src[idx4 + t * 256];
            uint4 u;
            u.x = f2tf32(v.x); u.y = f2tf32(v.y); u.z = f2tf32(v.z); u.w = f2tf32(v.w);
            dst[idx4 + t * 256] = *reinterpret_cast<float4*>(&u);
        }
    } else {
        // W12t: 128 blocks, each computes rows [rbase, rbase+8) of W12 for all 64 cols
        __shared__ float sW[8][256];
        int rbase = (b - NN - 512) * 8;
#pragma unroll
        for (int t = 0; t < 8; t++) {
            int idx = t * 256 + tid;
            sW[idx >> 8][idx & 255] = Wg1[(size_t)(rbase + (idx >> 8)) * HIDD + (idx & 255)];
        }
        __syncthreads();
        int c = tid & 63, rr = tid >> 6;   // rr 0..3
#pragma unroll
        for (int half = 0; half < 2; half++) {
            int rl = rr + half * 4;
            float acc = 0.f;
#pragma unroll 4
            for (int k = 0; k < HIDD; k++)
                acc = fmaf(sW[rl][k], __ldg(&Wl2[k * L2DIM + c]), acc);
            g_W12t[(size_t)c * IN_DIM + rbase + rl] = __uint_as_float(f2tf32(acc));
        }
    }
}

// ---------------- tf32 tensor-core GEMM, TMA loader, BK=64, 4-stage --------
#define BKK 64
#define HSB 8192      // half-stage bytes per operand (64 rows * 128B)
#define STGB 32768    // full stage (A 16KB + B 16KB)
#define NSTGT 4
#define STG_TX 32768
#define GEMM_SMEM (2048 + NSTGT * STGB)

template <bool TRANSOUT, int NSPLIT, bool SCALE, int CSTRIDE>
__device__ __forceinline__ void gemm_body(const CUtensorMap* mapA,
                                          const CUtensorMap* mapB,
                                          float* __restrict__ C, int Kd,
                                          const float* __restrict__ sumvec) {
    extern __shared__ __align__(16) uint8_t smem_dyn[];
    const uint32_t raw = (uint32_t)__cvta_generic_to_shared(smem_dyn);
    const uint32_t base0 = (raw + 1023u) & ~1023u;   // 1024-aligned for SW128
    const uint32_t barB = base0;                      // 4 mbarriers (8B apart)
    const uint32_t stg0 = base0 + 1024;

    const int tid = threadIdx.x;
    const int lane = tid & 31, warp = tid >> 5;
    const int wm = warp & 1, wn = (warp >> 1) & 1, kg = warp >> 2;  // kg 0..1
    const int gid = lane >> 2, tig = lane & 3;
    const int mi = lane >> 3, lr = lane & 7;
    const int bm0 = blockIdx.y * 64, bn0 = blockIdx.x * 64;
    const int kbase = (NSPLIT > 1) ? blockIdx.z * (Kd / NSPLIT) : 0;

    const int arow = wm * 32 + ((mi & 1) << 3) + lr;
    const int brow = wn * 32 + ((mi >> 1) << 3) + lr;
    const uint32_t axr = arow & 7, bxr = brow & 7;
    const uint32_t qselA = mi >> 1, qselB = mi & 1;
    const uint32_t aOff0 = arow * 128, aOff1 = aOff0 + 16 * 128;
    const uint32_t bOff0 = brow * 128, bOff1 = bOff0 + 16 * 128;
    const uint32_t aqj[2] = {(((uint32_t)(kg * 2 + 0) * 2 + qselA) ^ axr) << 4,
                             (((uint32_t)(kg * 2 + 1) * 2 + qselA) ^ axr) << 4};
    const uint32_t bqj[2] = {(((uint32_t)(kg * 2 + 0) * 2 + qselB) ^ bxr) << 4,
                             (((uint32_t)(kg * 2 + 1) * 2 + qselB) ^ bxr) << 4};

    if (tid == 0) {
#pragma unroll
        for (int s = 0; s < NSTGT; s++) mbar_init(barB + s * 8, 1);
        asm volatile("fence.proxy.async.shared::cta;" ::: "memory");
    }
    __syncthreads();

    auto issue = [&](int kt, int s) {   // tid==0 only
        uint32_t bar = barB + s * 8;
        uint32_t sa = stg0 + s * STGB;
        mbar_expect_tx(bar, STG_TX);
        int k0 = kbase + kt * BKK;
        tma2d(sa,               mapA, k0,      bm0, bar);
        tma2d(sa + HSB,         mapA, k0 + 32, bm0, bar);
        tma2d(sa + 2 * HSB,     mapB, k0,      bn0, bar);
        tma2d(sa + 3 * HSB,     mapB, k0 + 32, bn0, bar);
    };

    const int niter = (Kd / NSPLIT) / BKK;
    if (tid == 0) {
#pragma unroll
        for (int p = 0; p < NSTGT - 1; p++)
            if (p < niter) issue(p, p);
    }

    float acc[2][4][4] = {};
    uint32_t ph[NSTGT] = {};

    for (int i = 0; i < niter; i++) {
        const int s = i & (NSTGT - 1);
        mbar_wait(barB + s * 8, ph[s]);
        ph[s] ^= 1;
        const uint32_t sa = stg0 + s * STGB;
#pragma unroll
        for (int h = 0; h < 2; h++) {
            const uint32_t sAs = sa + h * HSB;
            const uint32_t sBs = sa + 2 * HSB + h * HSB;
#pragma unroll
            for (int jj = 0; jj < 2; jj++) {
                uint32_t af0[4], af1[4], bf0[4], bf1[4];
                ldsm4(af0, sAs + aOff0 + aqj[jj]);
                ldsm4(af1, sAs + aOff1 + aqj[jj]);
                ldsm4(bf0, sBs + bOff0 + bqj[jj]);
                ldsm4(bf1, sBs + bOff1 + bqj[jj]);
                mma_tf32(acc[0][0], af0, bf0[0], bf0[1]);
                mma_tf32(acc[0][1], af0, bf0[2], bf0[3]);
                mma_tf32(acc[0][2], af0, bf1[0], bf1[1]);
                mma_tf32(acc[0][3], af0, bf1[2], bf1[3]);
                mma_tf32(acc[1][0], af1, bf0[0], bf0[1]);
                mma_tf32(acc[1][1], af1, bf0[2], bf0[3]);
                mma_tf32(acc[1][2], af1, bf1[0], bf1[1]);
                mma_tf32(acc[1][3], af1, bf1[2], bf1[3]);
            }
        }
        __syncthreads();   // all warps done with stage s; slot (i-1)%4 now free
        if (i + NSTGT - 1 < niter && tid == 0)
            issue(i + NSTGT - 1, (i + NSTGT - 1) & (NSTGT - 1));
    }

    // ---- 2-way K-split reduction through smem (aliases stage region) ------
    float* sred = reinterpret_cast<float*>(smem_dyn + (stg0 - raw));
    const int pi = wm * 2 + wn;
    if (kg == 1) {
#pragma unroll
        for (int mt = 0; mt < 2; mt++)
#pragma unroll
            for (int nt = 0; nt < 4; nt++) {
                int r = mt * 16 + gid, c = nt * 8 + 2 * tig;
                float* basep = sred + pi * 1056;
                basep[r * 33 + c] = acc[mt][nt][0];
                basep[r * 33 + c + 1] = acc[mt][nt][1];
                basep[(r + 8) * 33 + c] = acc[mt][nt][2];
                basep[(r + 8) * 33 + c + 1] = acc[mt][nt][3];
            }
    }
    __syncthreads();
    if (kg == 0) {
#pragma unroll
        for (int mt = 0; mt < 2; mt++) {
            int r = mt * 16 + gid;
            const float* basep = sred + pi * 1056;
            int gr0 = bm0 + wm * 32 + r;
            int gr1 = gr0 + 8;
            float s0 = SCALE ? rsqrt_pos(sumvec[gr0]) : 1.f;
            float s1 = SCALE ? rsqrt_pos(sumvec[gr1]) : 1.f;
#pragma unroll
            for (int nt = 0; nt < 4; nt++) {
                int c = nt * 8 + 2 * tig;
                float v00 = (acc[mt][nt][0] + basep[r * 33 + c]) * s0;
                float v01 = (acc[mt][nt][1] + basep[r * 33 + c + 1]) * s0;
                float v10 = (acc[mt][nt][2] + basep[(r + 8) * 33 + c]) * s1;
                float v11 = (acc[mt][nt][3] + basep[(r + 8) * 33 + c + 1]) * s1;
                if (TRANSOUT) {
                    int n0 = bn0 + wn * 32 + c;
                    C[(size_t)n0 * NN + gr0] = __uint_as_float(f2tf32(v00));
                    C[(size_t)(n0 + 1) * NN + gr0] = __uint_as_float(f2tf32(v01));
                    C[(size_t)n0 * NN + gr1] = __uint_as_float(f2tf32(v10));
                    C[(size_t)(n0 + 1) * NN + gr1] = __uint_as_float(f2tf32(v11));
                } else {
                    int col = bn0 + wn * 32 + c;
                    *reinterpret_cast<float2*>(&C[(size_t)gr0 * CSTRIDE + col]) =
                        make_float2(v00, v01);
                    *reinterpret_cast<float2*>(&C[(size_t)gr1 * CSTRIDE + col]) =
                        make_float2(v10, v11);
                }
            }
        }
    }
}

// Y: g_Yt = (dc ⊙ (x @ W12))^T [64][2048], tf32; M=2048 N=64 K=1024
__global__ __launch_bounds__(256) void y_kernel(
    const __grid_constant__ CUtensorMap mA, const __grid_constant__ CUtensorMap mB) {
    gemm_body<true, 1, true, 0>(&mA, &mB, g_Yt, IN_DIM, g_colsum);
}
// HID-GEMM: g_Hp[z] = (g_A @ Y) partial over K-quarter z; M=2048 N=64 K=2048
__global__ __launch_bounds__(256) void hidg_kernel(
    const __grid_constant__ CUtensorMap mA, const __grid_constant__ CUtensorMap mB) {
    gemm_body<false, NSPL, false, L2DIM>(&mA, &mB, g_Hp[blockIdx.z], NN, nullptr);
}

// ---------------- finish: hid = dr*sum_z Hp + bl2;  HW = dc*(hid@Wg2) ------
__global__ __launch_bounds__(256) void hid_finish_kernel(const float* __restrict__ bl2,
                                                         const float* __restrict__ Wg2,
                                                         float* __restrict__ hid_out) {
    __shared__ float sHid[16][L2DIM + 1];
    int tid = threadIdx.x;
    int rowbase = blockIdx.x * 16;

    int c = tid & 63;
    int rq = tid >> 6;   // 0..3
    float b = bl2[c];
#pragma unroll
    for (int it = 0; it < 4; it++) {
        int row = it * 4 + rq;
        size_t idx = (size_t)(rowbase + row) * L2DIM + c;
        float v = 0.f;
#pragma unroll
        for (int z = 0; z < NSPL; z++) v += g_Hp[z][idx];
        v = v * rsqrt_pos(g_rowsum[rowbase + row]) + b;
        hid_out[idx] = v;
        sHid[row][c] = v;
    }
    __syncthreads();
    if (tid < 64) {
        int r = tid >> 2, cls = tid & 3;
        float s = 0.f;
#pragma unroll
        for (int k = 0; k < L2DIM; k++) s = fmaf(sHid[r][k], Wg2[k * NCLS + cls], s);
        g_HW[(size_t)(rowbase + r) * NCLS + cls] = s * rsqrt_pos(g_colsum[rowbase + r]);
    }
}

// ---------------- out[i] = dr[i] * sum_j A[i,j] * HW[j]; re-zero colsum ----
__global__ __launch_bounds__(256) void out_kernel(float* __restrict__ out) {
    int tid = threadIdx.x;
    // restore the colsum==0 invariant for the next graph replay
    // (hid_finish, the last consumer, has already completed)
    if (blockIdx.x == 0) {
#pragma unroll
        for (int t = 0; t < 8; t++) g_colsum[tid + t * 256] = 0.f;
    }
    __shared__ float sHWt[NCLS][NN];
    const float4* hw4 = reinterpret_cast<const float4*>(g_HW);
#pragma unroll
    for (int t = 0; t < NN / 256; t++) {
        int j = tid + t * 256;
        float4 h = hw4[j];            // HW row j: 4 classes
        sHWt[0][j] = h.x; sHWt[1][j] = h.y; sHWt[2][j] = h.z; sHWt[3][j] = h.w;
    }
    __syncthreads();

    const float4* A4 = reinterpret_cast<const float4*>(g_A);
    __shared__ float red[8][4];
    for (int r = 0; r < 8; r++) {
        int i = blockIdx.x * 8 + r;
        float ax = 0.f, ay = 0.f, az = 0.f, aw = 0.f;
#pragma unroll
        for (int t = 0; t < NN / 1024; t++) {
            int j4 = tid + t * 256;
            float4 a = A4[(size_t)i * (NN / 4) + j4];
            const float4 h0 = *reinterpret_cast<const float4*>(&sHWt[0][j4 * 4]);
            const float4 h1 = *reinterpret_cast<const float4*>(&sHWt[1][j4 * 4]);
            const float4 h2 = *reinterpret_cast<const float4*>(&sHWt[2][j4 * 4]);
            const float4 h3 = *reinterpret_cast<const float4*>(&sHWt[3][j4 * 4]);
            ax += a.x * h0.x + a.y * h0.y + a.z * h0.z + a.w * h0.w;
            ay += a.x * h1.x + a.y * h1.y + a.z * h1.z + a.w * h1.w;
            az += a.x * h2.x + a.y * h2.y + a.z * h2.z + a.w * h2.w;
            aw += a.x * h3.x + a.y * h3.y + a.z * h3.z + a.w * h3.w;
        }
        for (int off = 16; off; off >>= 1) {
            ax += __shfl_down_sync(0xffffffffu, ax, off);
            ay += __shfl_down_sync(0xffffffffu, ay, off);
            az += __shfl_down_sync(0xffffffffu, az, off);
            aw += __shfl_down_sync(0xffffffffu, aw, off);
        }
        if ((tid & 31) == 0) {
            int w = tid >> 5;
            red[w][0] = ax; red[w][1] = ay; red[w][2] = az; red[w][3] = aw;
        }
        __syncthreads();
        if (tid < 4) {
            float s = 0.f;
#pragma unroll
            for (int w = 0; w < 8; w++) s += red[w][tid];
            out[i * NCLS + tid] = rsqrt_pos(g_rowsum[i]) * s;
        }
        __syncthreads();
    }
}

// ---------------- host: tensor-map setup + launch --------------------------
typedef CUresult (*PFN_tmEncode)(
    CUtensorMap*, CUtensorMapDataType, cuuint32_t, void*,
    const cuuint64_t*, const cuuint64_t*, const cuuint32_t*, const cuuint32_t*,
    CUtensorMapInterleave, CUtensorMapSwizzle, CUtensorMapL2promotion,
    CUtensorMapFloatOOBfill);

extern "C" void kernel_launch(void* const* d_in, const int* in_sizes, int n_in,
                              void* d_out, int out_size) {
    const float* x    = (const float*)d_in[0];
    const float* adj  = (const float*)d_in[1];
    const float* xdeg = (const float*)d_in[2];
    const float* ydeg = (const float*)d_in[3];
    const float* Wm1  = (const float*)d_in[4];
    const float* bm1  = (const float*)d_in[5];
    const float* Wm2  = (const float*)d_in[6];
    const float* bm2  = (const float*)d_in[7];
    const float* Wg1  = (const float*)d_in[8];
    const float* Wl2  = (const float*)d_in[9];
    const float* bl2  = (const float*)d_in[10];
    const float* Wg2  = (const float*)d_in[11];

    float* out = (float*)d_out;               // [2048, 4]
    float* hid = out + (size_t)NN * NCLS;     // [2048, 64]

    static bool init_done = false;
    static CUtensorMap mA_y, mB_y, mA_h, mB_h;
    if (!init_done) {   // first call is the (uncaptured) correctness run
        cudaFuncSetAttribute(y_kernel,
                             cudaFuncAttributeMaxDynamicSharedMemorySize, GEMM_SMEM);
        cudaFuncSetAttribute(hidg_kernel,
                             cudaFuncAttributeMaxDynamicSharedMemorySize, GEMM_SMEM);
        void* fn = nullptr;
        cudaDriverEntryPointQueryResult qr;
        cudaGetDriverEntryPoint("cuTensorMapEncodeTiled", &fn,
                                cudaEnableDefault, &qr);
        PFN_tmEncode enc = (PFN_tmEncode)fn;
        void *pA, *pXt, *pW12t, *pYt;
        cudaGetSymbolAddress(&pA, g_A);
        cudaGetSymbolAddress(&pXt, g_Xt);
        cudaGetSymbolAddress(&pW12t, g_W12t);
        cudaGetSymbolAddress(&pYt, g_Yt);
        auto mk = [&](CUtensorMap* m, void* ptr, uint64_t d0, uint64_t d1) {
            cuuint64_t dims[2] = {d0, d1};
            cuuint64_t strides[1] = {d0 * 4};
            cuuint32_t box[2] = {32, 64};
            cuuint32_t es[2] = {1, 1};
            enc(m, CU_TENSOR_MAP_DATA_TYPE_FLOAT32, 2, ptr, dims, strides, box, es,
                CU_TENSOR_MAP_INTERLEAVE_NONE, CU_TENSOR_MAP_SWIZZLE_128B,
                CU_TENSOR_MAP_L2_PROMOTION_L2_128B,
                CU_TENSOR_MAP_FLOAT_OOB_FILL_NONE);
        };
        mk(&mA_y, pXt, IN_DIM, NN);
        mk(&mB_y, pW12t, IN_DIM, L2DIM);
        mk(&mA_h, pA, NN, NN);
        mk(&mB_h, pYt, NN, L2DIM);
        init_done = true;
    }

    edge_kernel<<<NN + 512 + 128, 256>>>(adj, xdeg, ydeg, Wm1, bm1, Wm2, bm2,
                                         x, Wg1, Wl2);
    y_kernel<<<dim3(1, NN / 64, 1), 256, GEMM_SMEM>>>(mA_y, mB_y);
    hidg_kernel<<<dim3(1, NN / 64, NSPL), 256, GEMM_SMEM>>>(mA_h, mB_h);
    hid_finish_kernel<<<NN / 16, 256>>>(bl2, Wg2, hid);
    out_kernel<<<NN / 8, 256>>>(out);
}

// round 16
// speedup vs baseline: 1.2503x; 1.0274x over previous
#include <cuda_runtime.h>
#include <cuda.h>
#include <cstdint>

#define NN 2048
#define IN_DIM 1024
#define MLPW 16
#define HIDD 256
#define L2DIM 64
#define NCLS 4
#define NSPL 4

// ---------------- scratch (device globals; no allocation) ----------------
__device__ float g_A[(size_t)NN * NN];          // A = adj*mask + I (tf32-rounded)
__device__ float g_Xt[(size_t)NN * IN_DIM];     // tf32-rounded x [2048][1024]
__device__ float g_W12t[(size_t)L2DIM * IN_DIM];// tf32 (Wg1@Wl2)^T [64][1024]
__device__ float g_Yt[(size_t)L2DIM * NN];      // tf32 (dc ⊙ x@W12)^T [64][2048]
__device__ float g_Hp[NSPL][(size_t)NN * L2DIM];// A@Y split-K partials (fp32)
__device__ float g_HW[(size_t)NN * NCLS];       // dc-scaled hid@Wg2
__device__ float g_rowsum[NN];
__device__ float g_colsum[NN];   // zero at load (.bss); re-zeroed by out_kernel

__device__ __forceinline__ float rsqrt_pos(float v) {
    return v > 0.f ? rsqrtf(v) : 0.f;
}
__device__ __forceinline__ uint32_t f2tf32(float f) {
    uint32_t u;
    asm("cvt.rna.tf32.f32 %0, %1;" : "=r"(u) : "f"(f));
    return u;
}

// ---------------- TMA / mbarrier / ldmatrix helpers ------------------------
__device__ __forceinline__ void tma2d(uint32_t dst, const CUtensorMap* m,
                                      int x, int y, uint32_t bar) {
    asm volatile(
        "cp.async.bulk.tensor.2d.shared::cta.global.tile.mbarrier::complete_tx::bytes "
        "[%0], [%1, {%2, %3}], [%4];"
        :: "r"(dst), "l"(m), "r"(x), "r"(y), "r"(bar) : "memory");
}
__device__ __forceinline__ void mbar_init(uint32_t bar, uint32_t cnt) {
    asm volatile("mbarrier.init.shared.b64 [%0], %1;" :: "r"(bar), "r"(cnt) : "memory");
}
__device__ __forceinline__ void mbar_expect_tx(uint32_t bar, uint32_t bytes) {
    asm volatile("mbarrier.arrive.expect_tx.shared.b64 _, [%0], %1;"
                 :: "r"(bar), "r"(bytes) : "memory");
}
__device__ __forceinline__ void mbar_wait(uint32_t bar, uint32_t parity) {
    uint32_t done;
    asm volatile(
        "{\n\t.reg .pred p;\n\t"
        "mbarrier.try_wait.parity.acquire.cta.shared::cta.b64 p, [%1], %2;\n\t"
        "selp.b32 %0, 1, 0, p;\n\t}"
        : "=r"(done) : "r"(bar), "r"(parity) : "memory");
    if (!done) {
        asm volatile(
            "{\n\t.reg .pred P1;\n\t"
            "WL_%=:\n\t"
            "mbarrier.try_wait.parity.acquire.cta.shared::cta.b64 P1, [%0], %1, 0x989680;\n\t"
            "@P1 bra.uni WD_%=;\n\t"
            "bra.uni WL_%=;\n\t"
            "WD_%=:\n\t}"
            :: "r"(bar), "r"(parity) : "memory");
    }
}
__device__ __forceinline__ void ldsm4(uint32_t* r, uint32_t addr) {
    asm volatile("ldmatrix.sync.aligned.m8n8.x4.shared.b16 {%0,%1,%2,%3}, [%4];"
                 : "=r"(r[0]), "=r"(r[1]), "=r"(r[2]), "=r"(r[3]) : "r"(addr));
}
__device__ __forceinline__ void mma_tf32(float* c,
                                         const uint32_t* a,
                                         uint32_t b0, uint32_t b1) {
    asm volatile(
        "mma.sync.aligned.m16n8k8.row.col.f32.tf32.tf32.f32 "
        "{%0,%1,%2,%3}, {%4,%5,%6,%7}, {%8,%9}, {%0,%1,%2,%3};"
        : "+f"(c[0]), "+f"(c[1]), "+f"(c[2]), "+f"(c[3])
        : "r"(a[0]), "r"(a[1]), "r"(a[2]), "r"(a[3]), "r"(b0), "r"(b1));
}

// ---------------- kernel 1: edge MLP + fused colsum + round x + W12t -------
__global__ __launch_bounds__(256) void edge_kernel(
    const float* __restrict__ adj, const float* __restrict__ xdeg,
    const float* __restrict__ ydeg, const float* __restrict__ Wm1,
    const float* __restrict__ bm1, const float* __restrict__ Wm2,
    const float* __restrict__ bm2, const float* __restrict__ x,
    const float* __restrict__ Wg1, const float* __restrict__ Wl2) {
    int b = blockIdx.x;
    int tid = threadIdx.x;
    if (b < NN) {
        __shared__ float sW1[48], sb1[16], sdw[16], sb2[2];
        if (tid < 48) sW1[tid] = Wm1[tid];
        if (tid < 16) sb1[tid] = bm1[tid];
        if (tid < 16) sdw[tid] = Wm2[2 * tid + 1] - Wm2[2 * tid];
        if (tid < 2)  sb2[tid] = bm2[tid];
        int i = b;
        __syncthreads();

        const float* arow = adj  + (size_t)i * NN;
        const float* xrow = xdeg + (size_t)i * NN;
        const float* yrow = ydeg + (size_t)i * NN;
        float* Arow = g_A + (size_t)i * NN;
        const float db = sb2[1] - sb2[0];

        float rsum = 0.f;
        float csum[8];
#pragma unroll
        for (int t = 0; t < 8; t++) csum[t] = 0.f;
#pragma unroll
        for (int t = 0; t < NN / 256; t++) {
            int j = tid + t * 256;
            float a = arow[j], xd = xrow[j], yd = yrow[j];
            float dl = db;
#pragma unroll
            for (int k = 0; k < MLPW; k++) {
                float h = fmaf(a, sW1[k], fmaf(xd, sW1[16 + k], fmaf(yd, sW1[32 + k], sb1[k])));
                h = fmaxf(h, 0.f);
                dl = fmaf(h, sdw[k], dl);
            }
            float d = 0.5f * dl;
            float th;
            asm("tanh.approx.f32 %0, %1;" : "=f"(th) : "f"(d));
            float mask = fmaf(0.5f, th, 0.5f);
            float Av = a * mask + (j == i ? 1.f : 0.f);
            Av = __uint_as_float(f2tf32(Av));
            Arow[j] = Av;
            rsum += Av;
            csum[t] = Av;
        }
        for (int off = 16; off; off >>= 1) rsum += __shfl_down_sync(0xffffffffu, rsum, off);
        __shared__ float red[8];
        if ((tid & 31) == 0) red[tid >> 5] = rsum;
        __syncthreads();
        if (tid == 0) {
            float s = 0.f;
#pragma unroll
            for (int w = 0; w < 8; w++) s += red[w];
            g_rowsum[i] = s;
        }
        // fused colsum: one atomic per (thread, column slot)
#pragma unroll
        for (int t = 0; t < 8; t++)
            atomicAdd(&g_colsum[tid + t * 256], csum[t]);
    } else if (b < NN + 512) {
        size_t idx4 = (size_t)(b - NN) * 1024 + tid;
        const float4* src = reinterpret_cast<const float4*>(x);
        float4* dst = reinterpret_cast<float4*>(g_Xt);
#pragma unroll
        for (int t = 0; t < 4; t++) {
            float4 v = src[idx4 + t * 256];
            uint4 u;
            u.x = f2tf32(v.x); u.y = f2tf32(v.y); u.z = f2tf32(v.z); u.w = f2tf32(v.w);
            dst[idx4 + t * 256] = *reinterpret_cast<float4*>(&u);
        }
    } else {
        // W12t: 128 blocks, each computes rows [rbase, rbase+8) of W12 for all 64 cols
        __shared__ float sW[8][256];
        int rbase = (b - NN - 512) * 8;
#pragma unroll
        for (int t = 0; t < 8; t++) {
            int idx = t * 256 + tid;
            sW[idx >> 8][idx & 255] = Wg1[(size_t)(rbase + (idx >> 8)) * HIDD + (idx & 255)];
        }
        __syncthreads();
        int c = tid & 63, rr = tid >> 6;   // rr 0..3
#pragma unroll
        for (int half = 0; half < 2; half++) {
            int rl = rr + half * 4;
            float acc = 0.f;
#pragma unroll 4
            for (int k = 0; k < HIDD; k++)
                acc = fmaf(sW[rl][k], __ldg(&Wl2[k * L2DIM + c]), acc);
            g_W12t[(size_t)c * IN_DIM + rbase + rl] = __uint_as_float(f2tf32(acc));
        }
    }
}

// ---------------- tf32 tensor-core GEMM, TMA loader, BK=64, 4-stage --------
#define BKK 64
#define HSB 8192      // half-stage bytes per operand (64 rows * 128B)
#define STGB 32768    // full stage (A 16KB + B 16KB)
#define NSTGT 4
#define STG_TX 32768
#define GEMM_SMEM (2048 + NSTGT * STGB)

template <bool TRANSOUT, int NSPLIT, bool SCALE, int CSTRIDE>
__device__ __forceinline__ void gemm_body(const CUtensorMap* mapA,
                                          const CUtensorMap* mapB,
                                          float* __restrict__ C, int Kd,
                                          const float* __restrict__ sumvec) {
    extern __shared__ __align__(16) uint8_t smem_dyn[];
    const uint32_t raw = (uint32_t)__cvta_generic_to_shared(smem_dyn);
    const uint32_t base0 = (raw + 1023u) & ~1023u;   // 1024-aligned for SW128
    const uint32_t barB = base0;                      // 4 mbarriers (8B apart)
    const uint32_t stg0 = base0 + 1024;

    const int tid = threadIdx.x;
    const int lane = tid & 31, warp = tid >> 5;
    const int wm = warp & 1, wn = (warp >> 1) & 1, kg = warp >> 2;  // kg 0..1
    const int gid = lane >> 2, tig = lane & 3;
    const int mi = lane >> 3, lr = lane & 7;
    const int bm0 = blockIdx.y * 64, bn0 = blockIdx.x * 64;
    const int kbase = (NSPLIT > 1) ? blockIdx.z * (Kd / NSPLIT) : 0;

    const int arow = wm * 32 + ((mi & 1) << 3) + lr;
    const int brow = wn * 32 + ((mi >> 1) << 3) + lr;
    const uint32_t axr = arow & 7, bxr = brow & 7;
    const uint32_t qselA = mi >> 1, qselB = mi & 1;
    const uint32_t aOff0 = arow * 128, aOff1 = aOff0 + 16 * 128;
    const uint32_t bOff0 = brow * 128, bOff1 = bOff0 + 16 * 128;
    const uint32_t aqj[2] = {(((uint32_t)(kg * 2 + 0) * 2 + qselA) ^ axr) << 4,
                             (((uint32_t)(kg * 2 + 1) * 2 + qselA) ^ axr) << 4};
    const uint32_t bqj[2] = {(((uint32_t)(kg * 2 + 0) * 2 + qselB) ^ bxr) << 4,
                             (((uint32_t)(kg * 2 + 1) * 2 + qselB) ^ bxr) << 4};

    if (tid == 0) {
#pragma unroll
        for (int s = 0; s < NSTGT; s++) mbar_init(barB + s * 8, 1);
        asm volatile("fence.proxy.async.shared::cta;" ::: "memory");
    }
    __syncthreads();

    auto issue = [&](int kt, int s) {   // tid==0 only
        uint32_t bar = barB + s * 8;
        uint32_t sa = stg0 + s * STGB;
        mbar_expect_tx(bar, STG_TX);
        int k0 = kbase + kt * BKK;
        tma2d(sa,               mapA, k0,      bm0, bar);
        tma2d(sa + HSB,         mapA, k0 + 32, bm0, bar);
        tma2d(sa + 2 * HSB,     mapB, k0,      bn0, bar);
        tma2d(sa + 3 * HSB,     mapB, k0 + 32, bn0, bar);
    };

    const int niter = (Kd / NSPLIT) / BKK;
    if (tid == 0) {
#pragma unroll
        for (int p = 0; p < NSTGT - 1; p++)
            if (p < niter) issue(p, p);
    }

    float acc[2][4][4] = {};
    uint32_t ph[NSTGT] = {};

    for (int i = 0; i < niter; i++) {
        const int s = i & (NSTGT - 1);
        mbar_wait(barB + s * 8, ph[s]);
        ph[s] ^= 1;
        const uint32_t sa = stg0 + s * STGB;
#pragma unroll
        for (int h = 0; h < 2; h++) {
            const uint32_t sAs = sa + h * HSB;
            const uint32_t sBs = sa + 2 * HSB + h * HSB;
#pragma unroll
            for (int jj = 0; jj < 2; jj++) {
                uint32_t af0[4], af1[4], bf0[4], bf1[4];
                ldsm4(af0, sAs + aOff0 + aqj[jj]);
                ldsm4(af1, sAs + aOff1 + aqj[jj]);
                ldsm4(bf0, sBs + bOff0 + bqj[jj]);
                ldsm4(bf1, sBs + bOff1 + bqj[jj]);
                mma_tf32(acc[0][0], af0, bf0[0], bf0[1]);
                mma_tf32(acc[0][1], af0, bf0[2], bf0[3]);
                mma_tf32(acc[0][2], af0, bf1[0], bf1[1]);
                mma_tf32(acc[0][3], af0, bf1[2], bf1[3]);
                mma_tf32(acc[1][0], af1, bf0[0], bf0[1]);
                mma_tf32(acc[1][1], af1, bf0[2], bf0[3]);
                mma_tf32(acc[1][2], af1, bf1[0], bf1[1]);
                mma_tf32(acc[1][3], af1, bf1[2], bf1[3]);
            }
        }
        __syncthreads();   // all warps done with stage s; slot (i-1)%4 now free
        if (i + NSTGT - 1 < niter && tid == 0)
            issue(i + NSTGT - 1, (i + NSTGT - 1) & (NSTGT - 1));
    }

    // ---- 2-way K-split reduction through smem (aliases stage region) ------
    float* sred = reinterpret_cast<float*>(smem_dyn + (stg0 - raw));
    const int pi = wm * 2 + wn;
    if (kg == 1) {
#pragma unroll
        for (int mt = 0; mt < 2; mt++)
#pragma unroll
            for (int nt = 0; nt < 4; nt++) {
                int r = mt * 16 + gid, c = nt * 8 + 2 * tig;
                float* basep = sred + pi * 1056;
                basep[r * 33 + c] = acc[mt][nt][0];
                basep[r * 33 + c + 1] = acc[mt][nt][1];
                basep[(r + 8) * 33 + c] = acc[mt][nt][2];
                basep[(r + 8) * 33 + c + 1] = acc[mt][nt][3];
            }
    }
    __syncthreads();
    if (kg == 0) {
#pragma unroll
        for (int mt = 0; mt < 2; mt++) {
            int r = mt * 16 + gid;
            const float* basep = sred + pi * 1056;
            int gr0 = bm0 + wm * 32 + r;
            int gr1 = gr0 + 8;
            float s0 = SCALE ? rsqrt_pos(sumvec[gr0]) : 1.f;
            float s1 = SCALE ? rsqrt_pos(sumvec[gr1]) : 1.f;
#pragma unroll
            for (int nt = 0; nt < 4; nt++) {
                int c = nt * 8 + 2 * tig;
                float v00 = (acc[mt][nt][0] + basep[r * 33 + c]) * s0;
                float v01 = (acc[mt][nt][1] + basep[r * 33 + c + 1]) * s0;
                float v10 = (acc[mt][nt][2] + basep[(r + 8) * 33 + c]) * s1;
                float v11 = (acc[mt][nt][3] + basep[(r + 8) * 33 + c + 1]) * s1;
                if (TRANSOUT) {
                    int n0 = bn0 + wn * 32 + c;
                    C[(size_t)n0 * NN + gr0] = __uint_as_float(f2tf32(v00));
                    C[(size_t)(n0 + 1) * NN + gr0] = __uint_as_float(f2tf32(v01));
                    C[(size_t)n0 * NN + gr1] = __uint_as_float(f2tf32(v10));
                    C[(size_t)(n0 + 1) * NN + gr1] = __uint_as_float(f2tf32(v11));
                } else {
                    int col = bn0 + wn * 32 + c;
                    *reinterpret_cast<float2*>(&C[(size_t)gr0 * CSTRIDE + col]) =
                        make_float2(v00, v01);
                    *reinterpret_cast<float2*>(&C[(size_t)gr1 * CSTRIDE + col]) =
                        make_float2(v10, v11);
                }
            }
        }
    }
}

// Y: g_Yt = (dc ⊙ (x @ W12))^T [64][2048], tf32; M=2048 N=64 K=1024
__global__ __launch_bounds__(256) void y_kernel(
    const __grid_constant__ CUtensorMap mA, const __grid_constant__ CUtensorMap mB) {
    gemm_body<true, 1, true, 0>(&mA, &mB, g_Yt, IN_DIM, g_colsum);
}
// HID-GEMM: g_Hp[z] = (g_A @ Y) partial over K-quarter z; M=2048 N=64 K=2048
__global__ __launch_bounds__(256) void hidg_kernel(
    const __grid_constant__ CUtensorMap mA, const __grid_constant__ CUtensorMap mB) {
    gemm_body<false, NSPL, false, L2DIM>(&mA, &mB, g_Hp[blockIdx.z], NN, nullptr);
}

// ---------------- finish: hid = dr*sum_z Hp + bl2;  HW = dc*(hid@Wg2) ------
// float4-vectorized: 128 blocks x 16 rows; tid indexes the 256 float4s directly
__global__ __launch_bounds__(256) void hid_finish_kernel(const float* __restrict__ bl2,
                                                         const float* __restrict__ Wg2,
                                                         float* __restrict__ hid_out) {
    __shared__ float sHid[16][L2DIM + 4];   // pitch 68 floats (16B-aligned rows)
    int tid = threadIdx.x;
    int rowbase = blockIdx.x * 16;

    int row = tid >> 4;          // 0..15
    int c4 = tid & 15;           // float4 column index
    size_t f4idx = (size_t)rowbase * 16 + tid;

    float4 v = reinterpret_cast<const float4*>(g_Hp[0])[f4idx];
#pragma unroll
    for (int z = 1; z < NSPL; z++) {
        float4 p = reinterpret_cast<const float4*>(g_Hp[z])[f4idx];
        v.x += p.x; v.y += p.y; v.z += p.z; v.w += p.w;
    }
    float dr = rsqrt_pos(g_rowsum[rowbase + row]);
    float4 bias = reinterpret_cast<const float4*>(bl2)[c4];
    v.x = fmaf(v.x, dr, bias.x);
    v.y = fmaf(v.y, dr, bias.y);
    v.z = fmaf(v.z, dr, bias.z);
    v.w = fmaf(v.w, dr, bias.w);
    reinterpret_cast<float4*>(hid_out)[f4idx] = v;
    *reinterpret_cast<float4*>(&sHid[row][c4 * 4]) = v;
    __syncthreads();

    if (tid < 64) {
        int r = tid >> 2, cls = tid & 3;
        float s = 0.f;
#pragma unroll
        for (int k = 0; k < L2DIM; k++) s = fmaf(sHid[r][k], Wg2[k * NCLS + cls], s);
        g_HW[(size_t)(rowbase + r) * NCLS + cls] = s * rsqrt_pos(g_colsum[rowbase + r]);
    }
}

// ---------------- out[i] = dr[i] * sum_j A[i,j] * HW[j]; re-zero colsum ----
// batched: all 8 rows accumulated concurrently (MLP 8), single reduction
__global__ __launch_bounds__(256) void out_kernel(float* __restrict__ out) {
    int tid = threadIdx.x;
    // restore the colsum==0 invariant for the next graph replay
    if (blockIdx.x == 0) {
#pragma unroll
        for (int t = 0; t < 8; t++) g_colsum[tid + t * 256] = 0.f;
    }
    __shared__ float sHWt[NCLS][NN];
    const float4* hw4 = reinterpret_cast<const float4*>(g_HW);
#pragma unroll
    for (int t = 0; t < NN / 256; t++) {
        int j = tid + t * 256;
        float4 h = hw4[j];            // HW row j: 4 classes
        sHWt[0][j] = h.x; sHWt[1][j] = h.y; sHWt[2][j] = h.z; sHWt[3][j] = h.w;
    }
    __syncthreads();

    const float4* A4 = reinterpret_cast<const float4*>(g_A);
    const int i0 = blockIdx.x * 8;
    float acc[8][4];
#pragma unroll
    for (int r = 0; r < 8; r++)
#pragma unroll
        for (int c = 0; c < 4; c++) acc[r][c] = 0.f;

#pragma unroll
    for (int t = 0; t < NN / 1024; t++) {
        int j4 = tid + t * 256;
        const float4 h0 = *reinterpret_cast<const float4*>(&sHWt[0][j4 * 4]);
        const float4 h1 = *reinterpret_cast<const float4*>(&sHWt[1][j4 * 4]);
        const float4 h2 = *reinterpret_cast<const float4*>(&sHWt[2][j4 * 4]);
        const float4 h3 = *reinterpret_cast<const float4*>(&sHWt[3][j4 * 4]);
#pragma unroll
        for (int r = 0; r < 8; r++) {
            float4 a = A4[(size_t)(i0 + r) * (NN / 4) + j4];
            acc[r][0] += a.x * h0.x + a.y * h0.y + a.z * h0.z + a.w * h0.w;
            acc[r][1] += a.x * h1.x + a.y * h1.y + a.z * h1.z + a.w * h1.w;
            acc[r][2] += a.x * h2.x + a.y * h2.y + a.z * h2.z + a.w * h2.w;
            acc[r][3] += a.x * h3.x + a.y * h3.y + a.z * h3.z + a.w * h3.w;
        }
    }

    __shared__ float red[8][8][4];   // [warp][row][cls]
#pragma unroll
    for (int r = 0; r < 8; r++) {
#pragma unroll
        for (int c = 0; c < 4; c++)
            for (int off = 16; off; off >>= 1)
                acc[r][c] += __shfl_down_sync(0xffffffffu, acc[r][c], off);
        if ((tid & 31) == 0) {
            int w = tid >> 5;
#pragma unroll
            for (int c = 0; c < 4; c++) red[w][r][c] = acc[r][c];
        }
    }
    __syncthreads();
    if (tid < 32) {
        int r = tid >> 2, cls = tid & 3;
        float s = 0.f;
#pragma unroll
        for (int w = 0; w < 8; w++) s += red[w][r][cls];
        out[(i0 + r) * NCLS + cls] = rsqrt_pos(g_rowsum[i0 + r]) * s;
    }
}

// ---------------- host: tensor-map setup + launch --------------------------
typedef CUresult (*PFN_tmEncode)(
    CUtensorMap*, CUtensorMapDataType, cuuint32_t, void*,
    const cuuint64_t*, const cuuint64_t*, const cuuint32_t*, const cuuint32_t*,
    CUtensorMapInterleave, CUtensorMapSwizzle, CUtensorMapL2promotion,
    CUtensorMapFloatOOBfill);

extern "C" void kernel_launch(void* const* d_in, const int* in_sizes, int n_in,
                              void* d_out, int out_size) {
    const float* x    = (const float*)d_in[0];
    const float* adj  = (const float*)d_in[1];
    const float* xdeg = (const float*)d_in[2];
    const float* ydeg = (const float*)d_in[3];
    const float* Wm1  = (const float*)d_in[4];
    const float* bm1  = (const float*)d_in[5];
    const float* Wm2  = (const float*)d_in[6];
    const float* bm2  = (const float*)d_in[7];
    const float* Wg1  = (const float*)d_in[8];
    const float* Wl2  = (const float*)d_in[9];
    const float* bl2  = (const float*)d_in[10];
    const float* Wg2  = (const float*)d_in[11];

    float* out = (float*)d_out;               // [2048, 4]
    float* hid = out + (size_t)NN * NCLS;     // [2048, 64]

    static bool init_done = false;
    static CUtensorMap mA_y, mB_y, mA_h, mB_h;
    if (!init_done) {   // first call is the (uncaptured) correctness run
        cudaFuncSetAttribute(y_kernel,
                             cudaFuncAttributeMaxDynamicSharedMemorySize, GEMM_SMEM);
        cudaFuncSetAttribute(hidg_kernel,
                             cudaFuncAttributeMaxDynamicSharedMemorySize, GEMM_SMEM);
        void* fn = nullptr;
        cudaDriverEntryPointQueryResult qr;
        cudaGetDriverEntryPoint("cuTensorMapEncodeTiled", &fn,
                                cudaEnableDefault, &qr);
        PFN_tmEncode enc = (PFN_tmEncode)fn;
        void *pA, *pXt, *pW12t, *pYt;
        cudaGetSymbolAddress(&pA, g_A);
        cudaGetSymbolAddress(&pXt, g_Xt);
        cudaGetSymbolAddress(&pW12t, g_W12t);
        cudaGetSymbolAddress(&pYt, g_Yt);
        auto mk = [&](CUtensorMap* m, void* ptr, uint64_t d0, uint64_t d1) {
            cuuint64_t dims[2] = {d0, d1};
            cuuint64_t strides[1] = {d0 * 4};
            cuuint32_t box[2] = {32, 64};
            cuuint32_t es[2] = {1, 1};
            enc(m, CU_TENSOR_MAP_DATA_TYPE_FLOAT32, 2, ptr, dims, strides, box, es,
                CU_TENSOR_MAP_INTERLEAVE_NONE, CU_TENSOR_MAP_SWIZZLE_128B,
                CU_TENSOR_MAP_L2_PROMOTION_L2_128B,
                CU_TENSOR_MAP_FLOAT_OOB_FILL_NONE);
        };
        mk(&mA_y, pXt, IN_DIM, NN);
        mk(&mB_y, pW12t, IN_DIM, L2DIM);
        mk(&mA_h, pA, NN, NN);
        mk(&mB_h, pYt, NN, L2DIM);
        init_done = true;
    }

    edge_kernel<<<NN + 512 + 128, 256>>>(adj, xdeg, ydeg, Wm1, bm1, Wm2, bm2,
                                         x, Wg1, Wl2);
    y_kernel<<<dim3(1, NN / 64, 1), 256, GEMM_SMEM>>>(mA_y, mB_y);
    hidg_kernel<<<dim3(1, NN / 64, NSPL), 256, GEMM_SMEM>>>(mA_h, mB_h);
    hid_finish_kernel<<<NN / 16, 256>>>(bl2, Wg2, hid);
    out_kernel<<<NN / 8, 256>>>(out);
}